// round 2
// baseline (speedup 1.0000x reference)
#include <cuda_runtime.h>
#include <cuda_bf16.h>
#include <cstdint>
#include <cstddef>

// Problem constants (fixed by the dataset)
#define S_TOK 8192      // B*T = 4*2048
#define M_DIM 512
#define H_DIM 1024
#define N_EXP 8
#define CAP   1024      // per-expert capacity

// ---------------- device scratch (static __device__ globals; no cudaMalloc) ----
__device__ float g_h[(size_t)N_EXP * CAP * H_DIM];     // expert hidden  [E,C,H] 33.6MB
__device__ float g_y[(size_t)N_EXP * CAP * M_DIM];     // expert out     [E,C,M] 16.8MB
__device__ float g_gates[(size_t)S_TOK * N_EXP];       // full softmax gates
__device__ float g_gate[S_TOK];                        // top-1 gate prob
__device__ int   g_expert[S_TOK];                      // top-1 expert id
__device__ int   g_loc[S_TOK];                         // slot within expert (may be >= CAP)
__device__ int   g_slot[N_EXP * CAP];                  // slot -> token (-1 empty)
__device__ int   g_kept[N_EXP];                        // kept token count per expert

// ---------------- 1) gating: logits = feats @ wg, softmax, argmax ---------------
__global__ void gate_kernel(const float* __restrict__ feats, const float* __restrict__ wg) {
    __shared__ float wgT[N_EXP * M_DIM];   // transposed: [e][m], conflict-free reads
    int tid = threadIdx.x;
    for (int i = tid; i < N_EXP * M_DIM; i += 256) {
        int m = i & (M_DIM - 1);
        int e = i >> 9;
        wgT[e * M_DIM + m] = wg[m * N_EXP + e];
    }
    __syncthreads();

    int warp = tid >> 5, lane = tid & 31;
    int s = blockIdx.x * 8 + warp;

    const float* frow = feats + (size_t)s * M_DIM;
    float x[16];
#pragma unroll
    for (int j = 0; j < 16; j++) x[j] = frow[lane + 32 * j];

    float logit[N_EXP];
#pragma unroll
    for (int e = 0; e < N_EXP; e++) {
        const float* w = wgT + e * M_DIM;
        float acc = 0.f;
#pragma unroll
        for (int j = 0; j < 16; j++) acc += x[j] * w[lane + 32 * j];
#pragma unroll
        for (int off = 16; off > 0; off >>= 1)
            acc += __shfl_down_sync(0xffffffffu, acc, off);
        logit[e] = acc;   // valid on lane 0
    }

    if (lane == 0) {
        float mx = logit[0]; int am = 0;
#pragma unroll
        for (int e = 1; e < N_EXP; e++)
            if (logit[e] > mx) { mx = logit[e]; am = e; }   // first-max, matches argmax
        float ex[N_EXP]; float se = 0.f;
#pragma unroll
        for (int e = 0; e < N_EXP; e++) { ex[e] = expf(logit[e] - mx); se += ex[e]; }
        float inv = 1.f / se;
#pragma unroll
        for (int e = 0; e < N_EXP; e++) g_gates[(size_t)s * N_EXP + e] = ex[e] * inv;
        g_expert[s] = am;
        g_gate[s]   = ex[am] * inv;
    }
}

// ---------------- 2) capacity scan (order of arrival), slot assignment ----------
__global__ void scan_kernel() {
    __shared__ int base[N_EXP];
    __shared__ int wcnt[N_EXP][8];
    int tid = threadIdx.x;
    for (int i = tid; i < N_EXP * CAP; i += 256) g_slot[i] = -1;
    if (tid < N_EXP) base[tid] = 0;
    __syncthreads();

    int warp = tid >> 5, lane = tid & 31;
    unsigned ltmask = (lane == 0) ? 0u : (0xffffffffu >> (32 - lane));

    for (int tile = 0; tile < S_TOK / 256; tile++) {
        int s = tile * 256 + tid;
        int e = g_expert[s];
        int myrank = 0;
#pragma unroll
        for (int eq = 0; eq < N_EXP; eq++) {
            unsigned bal = __ballot_sync(0xffffffffu, e == eq);
            if (e == eq) myrank = __popc(bal & ltmask);
            if (lane == 0) wcnt[eq][warp] = __popc(bal);
        }
        __syncthreads();
        int off = base[e];
        for (int w = 0; w < warp; w++) off += wcnt[e][w];
        int loc = off + myrank;
        g_loc[s] = loc;
        if (loc < CAP) g_slot[e * CAP + loc] = s;
        __syncthreads();
        if (tid < N_EXP) {
            int tot = 0;
#pragma unroll
            for (int w = 0; w < 8; w++) tot += wcnt[tid][w];
            base[tid] += tot;
        }
        __syncthreads();
    }
    if (tid < N_EXP) g_kept[tid] = min(base[tid], CAP);
}

// ---------------- 3) l_aux = E * sum_e mean(gates_e) * (kept_e / S) -------------
__global__ void laux_kernel(float* __restrict__ out_laux) {
    __shared__ float partial[256];
    float w[N_EXP];
#pragma unroll
    for (int e = 0; e < N_EXP; e++) w[e] = (float)g_kept[e];
    float acc = 0.f;
    for (int s = threadIdx.x; s < S_TOK; s += 256) {
#pragma unroll
        for (int e = 0; e < N_EXP; e++) acc += g_gates[(size_t)s * N_EXP + e] * w[e];
    }
    partial[threadIdx.x] = acc;
    __syncthreads();
    for (int st = 128; st > 0; st >>= 1) {
        if (threadIdx.x < st) partial[threadIdx.x] += partial[threadIdx.x + st];
        __syncthreads();
    }
    if (threadIdx.x == 0)
        *out_laux = partial[0] * (float)N_EXP / ((float)S_TOK * (float)S_TOK);
}

// ---------------- 4) GEMM1: gathered feats[slot] @ w1[e] + b1, ReLU -> g_h ------
// 128x128 tile, BK=8, 256 threads, 8x8 per thread.
__global__ void __launch_bounds__(256, 2)
gemm1_kernel(const float* __restrict__ feats, const float* __restrict__ w1,
             const float* __restrict__ b1) {
    const int e = blockIdx.z;
    const int mt = blockIdx.y;   // 0..7
    const int nt = blockIdx.x;   // 0..7
    __shared__ float As[8][128];
    __shared__ float Bs[8][128];

    int tid = threadIdx.x;
    int aRow = tid >> 1;
    int aCol = (tid & 1) * 4;
    int bRow = tid >> 5;
    int bCol = (tid & 31) * 4;
    int ty = tid >> 4, tx = tid & 15;

    int slot = g_slot[e * CAP + mt * 128 + aRow];
    const float* arow = (slot >= 0) ? (feats + (size_t)slot * M_DIM) : nullptr;
    const float* Bb   = w1 + (size_t)e * M_DIM * H_DIM + nt * 128;

    float acc[8][8];
#pragma unroll
    for (int i = 0; i < 8; i++)
#pragma unroll
        for (int j = 0; j < 8; j++) acc[i][j] = 0.f;

    for (int k0 = 0; k0 < M_DIM; k0 += 8) {
        float4 av = arow ? *(const float4*)(arow + k0 + aCol) : make_float4(0.f, 0.f, 0.f, 0.f);
        As[aCol + 0][aRow] = av.x; As[aCol + 1][aRow] = av.y;
        As[aCol + 2][aRow] = av.z; As[aCol + 3][aRow] = av.w;
        *(float4*)(&Bs[bRow][bCol]) = *(const float4*)(Bb + (size_t)(k0 + bRow) * H_DIM + bCol);
        __syncthreads();
#pragma unroll
        for (int k = 0; k < 8; k++) {
            float4 ra0 = *(const float4*)(&As[k][ty * 8]);
            float4 ra1 = *(const float4*)(&As[k][ty * 8 + 4]);
            float4 rb0 = *(const float4*)(&Bs[k][tx * 8]);
            float4 rb1 = *(const float4*)(&Bs[k][tx * 8 + 4]);
            float ra[8] = {ra0.x, ra0.y, ra0.z, ra0.w, ra1.x, ra1.y, ra1.z, ra1.w};
            float rb[8] = {rb0.x, rb0.y, rb0.z, rb0.w, rb1.x, rb1.y, rb1.z, rb1.w};
#pragma unroll
            for (int i = 0; i < 8; i++)
#pragma unroll
                for (int j = 0; j < 8; j++) acc[i][j] += ra[i] * rb[j];
        }
        __syncthreads();
    }

    float* Hb = g_h + (size_t)e * CAP * H_DIM + (size_t)(mt * 128) * H_DIM + nt * 128;
    const float* b1e = b1 + e * H_DIM + nt * 128;
#pragma unroll
    for (int i = 0; i < 8; i++) {
        int r = ty * 8 + i;
#pragma unroll
        for (int j = 0; j < 8; j += 4) {
            float4 v;
            v.x = fmaxf(acc[i][j + 0] + b1e[tx * 8 + j + 0], 0.f);
            v.y = fmaxf(acc[i][j + 1] + b1e[tx * 8 + j + 1], 0.f);
            v.z = fmaxf(acc[i][j + 2] + b1e[tx * 8 + j + 2], 0.f);
            v.w = fmaxf(acc[i][j + 3] + b1e[tx * 8 + j + 3], 0.f);
            *(float4*)(Hb + (size_t)r * H_DIM + tx * 8 + j) = v;
        }
    }
}

// ---------------- 5) GEMM2: g_h @ w2[e] + b2 -> g_y ----------------------------
__global__ void __launch_bounds__(256, 2)
gemm2_kernel(const float* __restrict__ w2, const float* __restrict__ b2) {
    const int e = blockIdx.z;
    const int mt = blockIdx.y;   // 0..7
    const int nt = blockIdx.x;   // 0..3
    __shared__ float As[8][128];
    __shared__ float Bs[8][128];

    int tid = threadIdx.x;
    int aRow = tid >> 1;
    int aCol = (tid & 1) * 4;
    int bRow = tid >> 5;
    int bCol = (tid & 31) * 4;
    int ty = tid >> 4, tx = tid & 15;

    const float* arow = g_h + (size_t)e * CAP * H_DIM + (size_t)(mt * 128 + aRow) * H_DIM;
    const float* Bb   = w2 + (size_t)e * H_DIM * M_DIM + nt * 128;

    float acc[8][8];
#pragma unroll
    for (int i = 0; i < 8; i++)
#pragma unroll
        for (int j = 0; j < 8; j++) acc[i][j] = 0.f;

    for (int k0 = 0; k0 < H_DIM; k0 += 8) {
        float4 av = *(const float4*)(arow + k0 + aCol);
        As[aCol + 0][aRow] = av.x; As[aCol + 1][aRow] = av.y;
        As[aCol + 2][aRow] = av.z; As[aCol + 3][aRow] = av.w;
        *(float4*)(&Bs[bRow][bCol]) = *(const float4*)(Bb + (size_t)(k0 + bRow) * M_DIM + bCol);
        __syncthreads();
#pragma unroll
        for (int k = 0; k < 8; k++) {
            float4 ra0 = *(const float4*)(&As[k][ty * 8]);
            float4 ra1 = *(const float4*)(&As[k][ty * 8 + 4]);
            float4 rb0 = *(const float4*)(&Bs[k][tx * 8]);
            float4 rb1 = *(const float4*)(&Bs[k][tx * 8 + 4]);
            float ra[8] = {ra0.x, ra0.y, ra0.z, ra0.w, ra1.x, ra1.y, ra1.z, ra1.w};
            float rb[8] = {rb0.x, rb0.y, rb0.z, rb0.w, rb1.x, rb1.y, rb1.z, rb1.w};
#pragma unroll
            for (int i = 0; i < 8; i++)
#pragma unroll
                for (int j = 0; j < 8; j++) acc[i][j] += ra[i] * rb[j];
        }
        __syncthreads();
    }

    float* Yb = g_y + (size_t)e * CAP * M_DIM + (size_t)(mt * 128) * M_DIM + nt * 128;
    const float* b2e = b2 + e * M_DIM + nt * 128;
#pragma unroll
    for (int i = 0; i < 8; i++) {
        int r = ty * 8 + i;
#pragma unroll
        for (int j = 0; j < 8; j += 4) {
            float4 v;
            v.x = acc[i][j + 0] + b2e[tx * 8 + j + 0];
            v.y = acc[i][j + 1] + b2e[tx * 8 + j + 1];
            v.z = acc[i][j + 2] + b2e[tx * 8 + j + 2];
            v.w = acc[i][j + 3] + b2e[tx * 8 + j + 3];
            *(float4*)(Yb + (size_t)r * M_DIM + tx * 8 + j) = v;
        }
    }
}

// ---------------- 6) combine: out[s] = gate_s * y[e, loc] (0 if dropped) --------
__global__ void combine_kernel(float* __restrict__ out) {
    int s = blockIdx.x;
    int tid = threadIdx.x;   // 128 threads, float4 each -> 512 floats
    int loc = g_loc[s];
    float4 v = make_float4(0.f, 0.f, 0.f, 0.f);
    if (loc < CAP) {
        int e = g_expert[s];
        float g = g_gate[s];
        const float4* yr = (const float4*)(g_y + (size_t)(e * CAP + loc) * M_DIM);
        v = yr[tid];
        v.x *= g; v.y *= g; v.z *= g; v.w *= g;
    }
    ((float4*)(out + (size_t)s * M_DIM))[tid] = v;
}

// ---------------- launch --------------------------------------------------------
extern "C" void kernel_launch(void* const* d_in, const int* in_sizes, int n_in,
                              void* d_out, int out_size) {
    const float* hs = (const float*)d_in[0];   // [4,2048,512]
    const float* wg = (const float*)d_in[1];   // [512,8]
    const float* w1 = (const float*)d_in[2];   // [8,512,1024]
    const float* b1 = (const float*)d_in[3];   // [8,1024]
    const float* w2 = (const float*)d_in[4];   // [8,1024,512]
    const float* b2 = (const float*)d_in[5];   // [8,512]
    float* out = (float*)d_out;

    gate_kernel<<<S_TOK / 8, 256>>>(hs, wg);
    scan_kernel<<<1, 256>>>();
    gemm1_kernel<<<dim3(H_DIM / 128, CAP / 128, N_EXP), 256>>>(hs, w1, b1);
    gemm2_kernel<<<dim3(M_DIM / 128, CAP / 128, N_EXP), 256>>>(w2, b2);
    combine_kernel<<<S_TOK, 128>>>(out);
    if (out_size > S_TOK * M_DIM)
        laux_kernel<<<1, 256>>>(out + (size_t)S_TOK * M_DIM);
}

// round 4
// speedup vs baseline: 1.9063x; 1.9063x over previous
#include <cuda_runtime.h>
#include <cuda_bf16.h>
#include <cstdint>
#include <cstddef>

// Problem constants
#define S_TOK 8192
#define M_DIM 512
#define H_DIM 1024
#define N_EXP 8
#define CAP   1024

// ---------------- portable PTX helpers (sm_103 baseline, no 'a' features) ------
__device__ __forceinline__ uint32_t smem_to_u32(const void* p) {
    uint32_t a;
    asm("{ .reg .u64 t; cvta.to.shared.u64 t, %1; cvt.u32.u64 %0, t; }" : "=r"(a) : "l"(p));
    return a;
}
#define CP_ASYNC16(dst, src) \
    asm volatile("cp.async.cg.shared.global [%0], [%1], 16;" :: "r"(dst), "l"(src))
#define CP_COMMIT() asm volatile("cp.async.commit_group;" ::: "memory")
#define CP_WAIT1()  asm volatile("cp.async.wait_group 1;" ::: "memory")
#define LDSM_X4(r, addr) \
    asm volatile("ldmatrix.sync.aligned.m8n8.x4.shared.b16 {%0,%1,%2,%3}, [%4];" \
        : "=r"((r)[0]), "=r"((r)[1]), "=r"((r)[2]), "=r"((r)[3]) : "r"(addr))
#define MMA_BF16(c, a, b0, b1) \
    asm volatile("mma.sync.aligned.m16n8k16.row.col.f32.bf16.bf16.f32 " \
        "{%0,%1,%2,%3}, {%4,%5,%6,%7}, {%8,%9}, {%0,%1,%2,%3};" \
        : "+f"((c)[0]), "+f"((c)[1]), "+f"((c)[2]), "+f"((c)[3]) \
        : "r"((a)[0]), "r"((a)[1]), "r"((a)[2]), "r"((a)[3]), "r"(b0), "r"(b1))

// ---------------- device scratch ------------------------------------------------
__device__ __nv_bfloat16 g_a_hi[(size_t)N_EXP * CAP * M_DIM];
__device__ __nv_bfloat16 g_a_lo[(size_t)N_EXP * CAP * M_DIM];
__device__ __nv_bfloat16 g_h_hi[(size_t)N_EXP * CAP * H_DIM];
__device__ __nv_bfloat16 g_h_lo[(size_t)N_EXP * CAP * H_DIM];
__device__ __nv_bfloat16 g_w1t_hi[(size_t)N_EXP * H_DIM * M_DIM];
__device__ __nv_bfloat16 g_w1t_lo[(size_t)N_EXP * H_DIM * M_DIM];
__device__ __nv_bfloat16 g_w2t_hi[(size_t)N_EXP * M_DIM * H_DIM];
__device__ __nv_bfloat16 g_w2t_lo[(size_t)N_EXP * M_DIM * H_DIM];
__device__ float g_gates[(size_t)S_TOK * N_EXP];
__device__ float g_gate[S_TOK];
__device__ int   g_expert[S_TOK];
__device__ int   g_loc[S_TOK];
__device__ int   g_slot[N_EXP * CAP];
__device__ int   g_kept[N_EXP];

// ---------------- 1) gating -----------------------------------------------------
__global__ void gate_kernel(const float* __restrict__ feats, const float* __restrict__ wg) {
    __shared__ float wgT[N_EXP * M_DIM];
    int tid = threadIdx.x;
    for (int i = tid; i < N_EXP * M_DIM; i += 256) {
        int m = i & (M_DIM - 1);
        int e = i >> 9;
        wgT[e * M_DIM + m] = wg[m * N_EXP + e];
    }
    __syncthreads();
    int warp = tid >> 5, lane = tid & 31;
    int s = blockIdx.x * 8 + warp;
    const float* frow = feats + (size_t)s * M_DIM;
    float x[16];
#pragma unroll
    for (int j = 0; j < 16; j++) x[j] = frow[lane + 32 * j];
    float logit[N_EXP];
#pragma unroll
    for (int e = 0; e < N_EXP; e++) {
        const float* w = wgT + e * M_DIM;
        float acc = 0.f;
#pragma unroll
        for (int j = 0; j < 16; j++) acc += x[j] * w[lane + 32 * j];
#pragma unroll
        for (int off = 16; off > 0; off >>= 1)
            acc += __shfl_down_sync(0xffffffffu, acc, off);
        logit[e] = acc;
    }
    if (lane == 0) {
        float mx = logit[0]; int am = 0;
#pragma unroll
        for (int e = 1; e < N_EXP; e++)
            if (logit[e] > mx) { mx = logit[e]; am = e; }
        float ex[N_EXP]; float se = 0.f;
#pragma unroll
        for (int e = 0; e < N_EXP; e++) { ex[e] = expf(logit[e] - mx); se += ex[e]; }
        float inv = 1.f / se;
#pragma unroll
        for (int e = 0; e < N_EXP; e++) g_gates[(size_t)s * N_EXP + e] = ex[e] * inv;
        g_expert[s] = am;
        g_gate[s]   = ex[am] * inv;
    }
}

// ---------------- 2) capacity scan ---------------------------------------------
__global__ void scan_kernel() {
    __shared__ int base[N_EXP];
    __shared__ int wcnt[N_EXP][8];
    int tid = threadIdx.x;
    for (int i = tid; i < N_EXP * CAP; i += 256) g_slot[i] = -1;
    if (tid < N_EXP) base[tid] = 0;
    __syncthreads();
    int warp = tid >> 5, lane = tid & 31;
    unsigned ltmask = (lane == 0) ? 0u : (0xffffffffu >> (32 - lane));
    for (int tile = 0; tile < S_TOK / 256; tile++) {
        int s = tile * 256 + tid;
        int e = g_expert[s];
        int myrank = 0;
#pragma unroll
        for (int eq = 0; eq < N_EXP; eq++) {
            unsigned bal = __ballot_sync(0xffffffffu, e == eq);
            if (e == eq) myrank = __popc(bal & ltmask);
            if (lane == 0) wcnt[eq][warp] = __popc(bal);
        }
        __syncthreads();
        int off = base[e];
        for (int w = 0; w < warp; w++) off += wcnt[e][w];
        int loc = off + myrank;
        g_loc[s] = loc;
        if (loc < CAP) g_slot[e * CAP + loc] = s;
        __syncthreads();
        if (tid < N_EXP) {
            int tot = 0;
#pragma unroll
            for (int w = 0; w < 8; w++) tot += wcnt[tid][w];
            base[tid] += tot;
        }
        __syncthreads();
    }
    if (tid < N_EXP) g_kept[tid] = min(base[tid], CAP);
}

// ---------------- 3) l_aux ------------------------------------------------------
__global__ void laux_kernel(float* __restrict__ out_laux) {
    __shared__ float partial[256];
    float w[N_EXP];
#pragma unroll
    for (int e = 0; e < N_EXP; e++) w[e] = (float)g_kept[e];
    float acc = 0.f;
    for (int s = threadIdx.x; s < S_TOK; s += 256) {
#pragma unroll
        for (int e = 0; e < N_EXP; e++) acc += g_gates[(size_t)s * N_EXP + e] * w[e];
    }
    partial[threadIdx.x] = acc;
    __syncthreads();
    for (int st = 128; st > 0; st >>= 1) {
        if (threadIdx.x < st) partial[threadIdx.x] += partial[threadIdx.x + st];
        __syncthreads();
    }
    if (threadIdx.x == 0)
        *out_laux = partial[0] * (float)N_EXP / ((float)S_TOK * (float)S_TOK);
}

// ---------------- 4) gather tokens -> split bf16 A ------------------------------
__global__ void gather_split_kernel(const float* __restrict__ feats) {
    int b = blockIdx.x;
    int tid = threadIdx.x;
    int token = g_slot[b];
    float4 v = make_float4(0.f, 0.f, 0.f, 0.f);
    if (token >= 0) v = ((const float4*)(feats + (size_t)token * M_DIM))[tid];
    __nv_bfloat162 h01 = __floats2bfloat162_rn(v.x, v.y);
    __nv_bfloat162 h23 = __floats2bfloat162_rn(v.z, v.w);
    __nv_bfloat162 l01 = __floats2bfloat162_rn(v.x - __bfloat162float(h01.x),
                                               v.y - __bfloat162float(h01.y));
    __nv_bfloat162 l23 = __floats2bfloat162_rn(v.z - __bfloat162float(h23.x),
                                               v.w - __bfloat162float(h23.y));
    uint2 hv, lv;
    hv.x = *reinterpret_cast<uint32_t*>(&h01); hv.y = *reinterpret_cast<uint32_t*>(&h23);
    lv.x = *reinterpret_cast<uint32_t*>(&l01); lv.y = *reinterpret_cast<uint32_t*>(&l23);
    ((uint2*)(g_a_hi + (size_t)b * M_DIM))[tid] = hv;
    ((uint2*)(g_a_lo + (size_t)b * M_DIM))[tid] = lv;
}

// ---------------- 5) weight transpose + split -----------------------------------
__global__ void transpose_split_kernel(const float* __restrict__ in,
                                       __nv_bfloat16* __restrict__ hi,
                                       __nv_bfloat16* __restrict__ lo,
                                       int R, int C) {
    __shared__ float t[32][33];
    int e = blockIdx.z;
    int r0 = blockIdx.y * 32, c0 = blockIdx.x * 32;
    const float* ine = in + (size_t)e * R * C;
#pragma unroll
    for (int i = 0; i < 4; i++)
        t[threadIdx.y + i * 8][threadIdx.x] =
            ine[(size_t)(r0 + threadIdx.y + i * 8) * C + c0 + threadIdx.x];
    __syncthreads();
    __nv_bfloat16* hie = hi + (size_t)e * R * C;
    __nv_bfloat16* loe = lo + (size_t)e * R * C;
#pragma unroll
    for (int i = 0; i < 4; i++) {
        int orow = c0 + threadIdx.y + i * 8;
        int ocol = r0 + threadIdx.x;
        float v = t[threadIdx.x][threadIdx.y + i * 8];
        __nv_bfloat16 h = __float2bfloat16(v);
        hie[(size_t)orow * R + ocol] = h;
        loe[(size_t)orow * R + ocol] = __float2bfloat16(v - __bfloat162float(h));
    }
}

// ---------------- 6) zero output ------------------------------------------------
__global__ void zero_out_kernel(float4* __restrict__ out) {
    out[(size_t)blockIdx.x * 256 + threadIdx.x] = make_float4(0.f, 0.f, 0.f, 0.f);
}

// ---------------- 7) split-bf16 GEMM via mma.sync (HMMA) ------------------------
// CTA tile 128x128, BK=32, 3-stage cp.async pipeline.
// SMEM per stage: Ahi(8KB) Alo(8KB) Bhi(8KB) Blo(8KB) = 32KB; rows of 32 bf16
// (64B) with 16B-segment swizzle seg ^= (row>>1)&3 (conflict-free ldmatrix).
// 8 warps as 2(m) x 4(n); warp tile 64x32 -> 4 mfrag x 4 nfrag m16n8k16.
template <int KTOT, bool IS_G1>
__global__ void __launch_bounds__(256, 1)
moe_gemm_mma(const __nv_bfloat16* __restrict__ a_hi, const __nv_bfloat16* __restrict__ a_lo,
             const __nv_bfloat16* __restrict__ b_hi, const __nv_bfloat16* __restrict__ b_lo,
             const float* __restrict__ bias, float* __restrict__ out) {
    constexpr int NTOT = IS_G1 ? H_DIM : M_DIM;
    constexpr int BK = 32;
    constexpr int NC = KTOT / BK;
    constexpr int STG = 32768;
    extern __shared__ __align__(1024) char smem[];
    const uint32_t sbu = smem_to_u32(smem);

    const int t = threadIdx.x;
    const int lane = t & 31, wid = t >> 5;
    const int wm = wid >> 2, wn = wid & 3;
    const int e = blockIdx.z, mt = blockIdx.y, nt = blockIdx.x;

    const __nv_bfloat16* srcs[4] = {
        a_hi + ((size_t)e * CAP  + mt * 128) * KTOT,
        a_lo + ((size_t)e * CAP  + mt * 128) * KTOT,
        b_hi + ((size_t)e * NTOT + nt * 128) * KTOT,
        b_lo + ((size_t)e * NTOT + nt * 128) * KTOT};

    // ---- async stage loader: 8 x 16B per thread --------------------------------
    auto load_stage = [&](int c, int stg) {
        int k0 = c * BK;
        uint32_t sb = sbu + stg * STG;
#pragma unroll
        for (int i = 0; i < 8; i++) {
            int idx  = i * 256 + t;
            int tile = idx >> 9;            // 0..3
            int row  = (idx >> 2) & 127;    // 0..127
            int seg  = idx & 3;             // 0..3 (16B units)
            const __nv_bfloat16* src = srcs[tile] + (size_t)row * KTOT + k0 + seg * 8;
            uint32_t dst = sb + tile * 8192 + row * 64 + ((seg ^ ((row >> 1) & 3)) << 4);
            CP_ASYNC16(dst, src);
        }
        CP_COMMIT();
    };

    float acc[4][4][4];
#pragma unroll
    for (int i = 0; i < 4; i++)
#pragma unroll
        for (int j = 0; j < 4; j++)
#pragma unroll
            for (int k = 0; k < 4; k++) acc[i][j][k] = 0.f;

    load_stage(0, 0);
    load_stage(1, 1);

    // per-thread ldmatrix row indices
    const int a_m   = wm * 64 + (lane & 15);         // + mf*16
    const int b_n   = wn * 32 + ((lane >> 3) & 1) * 8 + (lane & 7);  // + p*16
    const int k8l   = lane >> 4;                     // 0/1: k-half select

    int stg = 0;
    for (int c = 0; c < NC; c++) {
        CP_WAIT1();
        __syncthreads();
        if (c + 2 < NC) load_stage(c + 2, (c + 2) % 3);

        uint32_t sb = sbu + stg * STG;
#pragma unroll
        for (int ks = 0; ks < 2; ks++) {     // two k16 steps in BK=32
            uint32_t Ah[4][4], Al[4][4], Bh[2][4], Bl[2][4];
#pragma unroll
            for (int mf = 0; mf < 4; mf++) {
                int m = a_m + mf * 16;
                uint32_t off = sb + m * 64 + ((((ks << 1) + k8l) ^ ((m >> 1) & 3)) << 4);
                LDSM_X4(Ah[mf], off);
                LDSM_X4(Al[mf], off + 8192);
            }
#pragma unroll
            for (int p = 0; p < 2; p++) {
                int n = b_n + p * 16;
                uint32_t off = sb + 16384 + n * 64 + ((((ks << 1) + k8l) ^ ((n >> 1) & 3)) << 4);
                LDSM_X4(Bh[p], off);
                LDSM_X4(Bl[p], off + 8192);
            }
            // pass 1: Ahi*Bhi ; pass 2: Ahi*Blo ; pass 3: Alo*Bhi
#pragma unroll
            for (int mf = 0; mf < 4; mf++) {
#pragma unroll
                for (int p = 0; p < 2; p++) {
                    MMA_BF16(acc[mf][2 * p + 0], Ah[mf], Bh[p][0], Bh[p][2]);
                    MMA_BF16(acc[mf][2 * p + 1], Ah[mf], Bh[p][1], Bh[p][3]);
                    MMA_BF16(acc[mf][2 * p + 0], Ah[mf], Bl[p][0], Bl[p][2]);
                    MMA_BF16(acc[mf][2 * p + 1], Ah[mf], Bl[p][1], Bl[p][3]);
                    MMA_BF16(acc[mf][2 * p + 0], Al[mf], Bh[p][0], Bh[p][2]);
                    MMA_BF16(acc[mf][2 * p + 1], Al[mf], Bh[p][1], Bh[p][3]);
                }
            }
        }
        __syncthreads();
        stg = (stg + 1 == 3) ? 0 : stg + 1;
    }

    // ---- epilogue --------------------------------------------------------------
    const int g = lane >> 2, q = lane & 3;
    if (IS_G1) {
#pragma unroll
        for (int mf = 0; mf < 4; mf++) {
#pragma unroll
            for (int h = 0; h < 2; h++) {
                int slotrow = mt * 128 + wm * 64 + mf * 16 + g + h * 8;
                size_t rowbase = ((size_t)e * CAP + slotrow) * H_DIM;
#pragma unroll
                for (int nf = 0; nf < 4; nf++) {
                    int col = nt * 128 + wn * 32 + nf * 8 + q * 2;
                    float v0 = fmaxf(acc[mf][nf][2 * h + 0] + __ldg(&bias[e * NTOT + col]),     0.f);
                    float v1 = fmaxf(acc[mf][nf][2 * h + 1] + __ldg(&bias[e * NTOT + col + 1]), 0.f);
                    __nv_bfloat162 hh = __floats2bfloat162_rn(v0, v1);
                    __nv_bfloat162 ll = __floats2bfloat162_rn(v0 - __bfloat162float(hh.x),
                                                              v1 - __bfloat162float(hh.y));
                    *reinterpret_cast<uint32_t*>(&g_h_hi[rowbase + col]) =
                        *reinterpret_cast<uint32_t*>(&hh);
                    *reinterpret_cast<uint32_t*>(&g_h_lo[rowbase + col]) =
                        *reinterpret_cast<uint32_t*>(&ll);
                }
            }
        }
    } else {
#pragma unroll
        for (int mf = 0; mf < 4; mf++) {
#pragma unroll
            for (int h = 0; h < 2; h++) {
                int slotrow = mt * 128 + wm * 64 + mf * 16 + g + h * 8;
                int token = g_slot[e * CAP + slotrow];
                if (token < 0) continue;
                float gt = g_gate[token];
                float* orow = out + (size_t)token * M_DIM;
#pragma unroll
                for (int nf = 0; nf < 4; nf++) {
                    int col = nt * 128 + wn * 32 + nf * 8 + q * 2;
                    float2 v;
                    v.x = (acc[mf][nf][2 * h + 0] + __ldg(&bias[e * NTOT + col]))     * gt;
                    v.y = (acc[mf][nf][2 * h + 1] + __ldg(&bias[e * NTOT + col + 1])) * gt;
                    *(float2*)(orow + col) = v;
                }
            }
        }
    }
}

// ---------------- launch --------------------------------------------------------
extern "C" void kernel_launch(void* const* d_in, const int* in_sizes, int n_in,
                              void* d_out, int out_size) {
    const float* hs = (const float*)d_in[0];
    const float* wg = (const float*)d_in[1];
    const float* w1 = (const float*)d_in[2];   // [E, M, H]
    const float* b1 = (const float*)d_in[3];
    const float* w2 = (const float*)d_in[4];   // [E, H, M]
    const float* b2 = (const float*)d_in[5];
    float* out = (float*)d_out;

    constexpr int SMEM_BYTES = 3 * 32768;
    cudaFuncSetAttribute(moe_gemm_mma<M_DIM, true>,
                         cudaFuncAttributeMaxDynamicSharedMemorySize, SMEM_BYTES);
    cudaFuncSetAttribute(moe_gemm_mma<H_DIM, false>,
                         cudaFuncAttributeMaxDynamicSharedMemorySize, SMEM_BYTES);

    __nv_bfloat16 *a_hi, *a_lo, *h_hi, *h_lo, *w1t_hi, *w1t_lo, *w2t_hi, *w2t_lo;
    cudaGetSymbolAddress((void**)&a_hi, g_a_hi);
    cudaGetSymbolAddress((void**)&a_lo, g_a_lo);
    cudaGetSymbolAddress((void**)&h_hi, g_h_hi);
    cudaGetSymbolAddress((void**)&h_lo, g_h_lo);
    cudaGetSymbolAddress((void**)&w1t_hi, g_w1t_hi);
    cudaGetSymbolAddress((void**)&w1t_lo, g_w1t_lo);
    cudaGetSymbolAddress((void**)&w2t_hi, g_w2t_hi);
    cudaGetSymbolAddress((void**)&w2t_lo, g_w2t_lo);

    gate_kernel<<<S_TOK / 8, 256>>>(hs, wg);
    scan_kernel<<<1, 256>>>();
    transpose_split_kernel<<<dim3(H_DIM / 32, M_DIM / 32, N_EXP), dim3(32, 8)>>>(
        w1, w1t_hi, w1t_lo, M_DIM, H_DIM);   // [E,M,H] -> [E,H,M]
    transpose_split_kernel<<<dim3(M_DIM / 32, H_DIM / 32, N_EXP), dim3(32, 8)>>>(
        w2, w2t_hi, w2t_lo, H_DIM, M_DIM);   // [E,H,M] -> [E,M,H]
    gather_split_kernel<<<N_EXP * CAP, 128>>>(hs);
    zero_out_kernel<<<(S_TOK * M_DIM) / (4 * 256), 256>>>((float4*)out);

    moe_gemm_mma<M_DIM, true><<<dim3(H_DIM / 128, CAP / 128, N_EXP), 256, SMEM_BYTES>>>(
        a_hi, a_lo, w1t_hi, w1t_lo, b1, nullptr);
    moe_gemm_mma<H_DIM, false><<<dim3(M_DIM / 128, CAP / 128, N_EXP), 256, SMEM_BYTES>>>(
        h_hi, h_lo, w2t_hi, w2t_lo, b2, out);

    if (out_size > S_TOK * M_DIM)
        laux_kernel<<<1, 256>>>(out + (size_t)S_TOK * M_DIM);
}

// round 5
// speedup vs baseline: 3.3777x; 1.7719x over previous
#include <cuda_runtime.h>
#include <cuda_bf16.h>
#include <cuda_fp16.h>
#include <cstdint>
#include <cstddef>

// Problem constants
#define S_TOK 8192
#define M_DIM 512
#define H_DIM 1024
#define N_EXP 8
#define CAP   1024

// ---------------- portable PTX helpers (sm_103 baseline) ------------------------
__device__ __forceinline__ uint32_t smem_to_u32(const void* p) {
    uint32_t a;
    asm("{ .reg .u64 t; cvta.to.shared.u64 t, %1; cvt.u32.u64 %0, t; }" : "=r"(a) : "l"(p));
    return a;
}
#define CP_ASYNC16(dst, src) \
    asm volatile("cp.async.cg.shared.global [%0], [%1], 16;" :: "r"(dst), "l"(src))
#define CP_COMMIT() asm volatile("cp.async.commit_group;" ::: "memory")
#define CP_WAIT1()  asm volatile("cp.async.wait_group 1;" ::: "memory")
#define LDSM_X4(r, addr) \
    asm volatile("ldmatrix.sync.aligned.m8n8.x4.shared.b16 {%0,%1,%2,%3}, [%4];" \
        : "=r"((r)[0]), "=r"((r)[1]), "=r"((r)[2]), "=r"((r)[3]) : "r"(addr))
#define MMA_F16(c, a, b0, b1) \
    asm volatile("mma.sync.aligned.m16n8k16.row.col.f32.f16.f16.f32 " \
        "{%0,%1,%2,%3}, {%4,%5,%6,%7}, {%8,%9}, {%0,%1,%2,%3};" \
        : "+f"((c)[0]), "+f"((c)[1]), "+f"((c)[2]), "+f"((c)[3]) \
        : "r"((a)[0]), "r"((a)[1]), "r"((a)[2]), "r"((a)[3]), "r"(b0), "r"(b1))

// ---------------- device scratch ------------------------------------------------
__device__ __half g_a[(size_t)N_EXP * CAP * M_DIM];            // gathered tokens fp16
__device__ __half g_h[(size_t)N_EXP * CAP * H_DIM];            // hidden fp16
__device__ __half g_w1t[(size_t)N_EXP * H_DIM * M_DIM];        // w1^T fp16 [E,H,M]
__device__ __half g_w2t[(size_t)N_EXP * M_DIM * H_DIM];        // w2^T fp16 [E,M,H]
__device__ float g_gates[(size_t)S_TOK * N_EXP];
__device__ float g_gate[S_TOK];
__device__ int   g_expert[S_TOK];
__device__ int   g_loc[S_TOK];
__device__ int   g_slot[N_EXP * CAP];
__device__ int   g_kept[N_EXP];

// ---------------- 1) gating -----------------------------------------------------
__global__ void gate_kernel(const float* __restrict__ feats, const float* __restrict__ wg) {
    __shared__ float wgT[N_EXP * M_DIM];
    int tid = threadIdx.x;
    for (int i = tid; i < N_EXP * M_DIM; i += 256) {
        int m = i & (M_DIM - 1);
        int e = i >> 9;
        wgT[e * M_DIM + m] = wg[m * N_EXP + e];
    }
    __syncthreads();
    int warp = tid >> 5, lane = tid & 31;
    int s = blockIdx.x * 8 + warp;
    const float* frow = feats + (size_t)s * M_DIM;
    float x[16];
#pragma unroll
    for (int j = 0; j < 16; j++) x[j] = frow[lane + 32 * j];
    float logit[N_EXP];
#pragma unroll
    for (int e = 0; e < N_EXP; e++) {
        const float* w = wgT + e * M_DIM;
        float acc = 0.f;
#pragma unroll
        for (int j = 0; j < 16; j++) acc += x[j] * w[lane + 32 * j];
#pragma unroll
        for (int off = 16; off > 0; off >>= 1)
            acc += __shfl_down_sync(0xffffffffu, acc, off);
        logit[e] = acc;
    }
    if (lane == 0) {
        float mx = logit[0]; int am = 0;
#pragma unroll
        for (int e = 1; e < N_EXP; e++)
            if (logit[e] > mx) { mx = logit[e]; am = e; }
        float ex[N_EXP]; float se = 0.f;
#pragma unroll
        for (int e = 0; e < N_EXP; e++) { ex[e] = expf(logit[e] - mx); se += ex[e]; }
        float inv = 1.f / se;
#pragma unroll
        for (int e = 0; e < N_EXP; e++) g_gates[(size_t)s * N_EXP + e] = ex[e] * inv;
        g_expert[s] = am;
        g_gate[s]   = ex[am] * inv;
    }
}

// ---------------- 2) capacity scan ---------------------------------------------
__global__ void scan_kernel() {
    __shared__ int base[N_EXP];
    __shared__ int wcnt[N_EXP][8];
    int tid = threadIdx.x;
    for (int i = tid; i < N_EXP * CAP; i += 256) g_slot[i] = -1;
    if (tid < N_EXP) base[tid] = 0;
    __syncthreads();
    int warp = tid >> 5, lane = tid & 31;
    unsigned ltmask = (lane == 0) ? 0u : (0xffffffffu >> (32 - lane));
    for (int tile = 0; tile < S_TOK / 256; tile++) {
        int s = tile * 256 + tid;
        int e = g_expert[s];
        int myrank = 0;
#pragma unroll
        for (int eq = 0; eq < N_EXP; eq++) {
            unsigned bal = __ballot_sync(0xffffffffu, e == eq);
            if (e == eq) myrank = __popc(bal & ltmask);
            if (lane == 0) wcnt[eq][warp] = __popc(bal);
        }
        __syncthreads();
        int off = base[e];
        for (int w = 0; w < warp; w++) off += wcnt[e][w];
        int loc = off + myrank;
        g_loc[s] = loc;
        if (loc < CAP) g_slot[e * CAP + loc] = s;
        __syncthreads();
        if (tid < N_EXP) {
            int tot = 0;
#pragma unroll
            for (int w = 0; w < 8; w++) tot += wcnt[tid][w];
            base[tid] += tot;
        }
        __syncthreads();
    }
    if (tid < N_EXP) g_kept[tid] = min(base[tid], CAP);
}

// ---------------- 3) l_aux ------------------------------------------------------
__global__ void laux_kernel(float* __restrict__ out_laux) {
    __shared__ float partial[256];
    float w[N_EXP];
#pragma unroll
    for (int e = 0; e < N_EXP; e++) w[e] = (float)g_kept[e];
    float acc = 0.f;
    for (int s = threadIdx.x; s < S_TOK; s += 256) {
#pragma unroll
        for (int e = 0; e < N_EXP; e++) acc += g_gates[(size_t)s * N_EXP + e] * w[e];
    }
    partial[threadIdx.x] = acc;
    __syncthreads();
    for (int st = 128; st > 0; st >>= 1) {
        if (threadIdx.x < st) partial[threadIdx.x] += partial[threadIdx.x + st];
        __syncthreads();
    }
    if (threadIdx.x == 0)
        *out_laux = partial[0] * (float)N_EXP / ((float)S_TOK * (float)S_TOK);
}

// ---------------- 4) gather tokens -> fp16 A ------------------------------------
__global__ void gather_half_kernel(const float* __restrict__ feats) {
    int b = blockIdx.x;
    int tid = threadIdx.x;   // 128 threads x float4 = 512
    int token = g_slot[b];
    float4 v = make_float4(0.f, 0.f, 0.f, 0.f);
    if (token >= 0) v = ((const float4*)(feats + (size_t)token * M_DIM))[tid];
    __half2 h01 = __floats2half2_rn(v.x, v.y);
    __half2 h23 = __floats2half2_rn(v.z, v.w);
    uint2 hv;
    hv.x = *reinterpret_cast<uint32_t*>(&h01);
    hv.y = *reinterpret_cast<uint32_t*>(&h23);
    ((uint2*)(g_a + (size_t)b * M_DIM))[tid] = hv;
}

// ---------------- 5) weight transpose -> fp16: in[E][R][C] -> out[E][C][R] ------
__global__ void transpose_half_kernel(const float* __restrict__ in,
                                      __half* __restrict__ outw, int R, int C) {
    __shared__ float t[32][33];
    int e = blockIdx.z;
    int r0 = blockIdx.y * 32, c0 = blockIdx.x * 32;
    const float* ine = in + (size_t)e * R * C;
#pragma unroll
    for (int i = 0; i < 4; i++)
        t[threadIdx.y + i * 8][threadIdx.x] =
            ine[(size_t)(r0 + threadIdx.y + i * 8) * C + c0 + threadIdx.x];
    __syncthreads();
    __half* oe = outw + (size_t)e * R * C;
#pragma unroll
    for (int i = 0; i < 4; i++) {
        int orow = c0 + threadIdx.y + i * 8;
        int ocol = r0 + threadIdx.x;
        oe[(size_t)orow * R + ocol] = __float2half(t[threadIdx.x][threadIdx.y + i * 8]);
    }
}

// ---------------- 6) zero output ------------------------------------------------
__global__ void zero_out_kernel(float4* __restrict__ out) {
    out[(size_t)blockIdx.x * 256 + threadIdx.x] = make_float4(0.f, 0.f, 0.f, 0.f);
}

// ---------------- 7) single-pass fp16 GEMM via mma.sync -------------------------
// CTA tile 128x128, BK=64, 3-stage cp.async pipeline.
// Stage: A(16KB) + B(16KB); 128B rows (64 fp16), swizzle seg ^= row&7.
// 8 warps as 2(m) x 4(n); warp tile 64x32; per k16: 4mf x 2p x 2 = 16 MMAs.
template <int KTOT, bool IS_G1>
__global__ void __launch_bounds__(256, 1)
moe_gemm_f16(const __half* __restrict__ a_in, const __half* __restrict__ b_in,
             const float* __restrict__ bias, float* __restrict__ out) {
    constexpr int NTOT = IS_G1 ? H_DIM : M_DIM;
    constexpr int BK = 64;
    constexpr int NC = KTOT / BK;
    constexpr int STG = 32768;
    extern __shared__ __align__(1024) char smem[];
    const uint32_t sbu = smem_to_u32(smem);

    const int t = threadIdx.x;
    const int lane = t & 31, wid = t >> 5;
    const int wm = wid >> 2, wn = wid & 3;
    const int e = blockIdx.z, mt = blockIdx.y, nt = blockIdx.x;

    const __half* srcs[2] = {
        a_in + ((size_t)e * CAP  + mt * 128) * KTOT,
        b_in + ((size_t)e * NTOT + nt * 128) * KTOT};

    // ---- async stage loader: 8 x 16B per thread (2 tiles x 16KB) ---------------
    auto load_stage = [&](int c, int stg) {
        int k0 = c * BK;
        uint32_t sb = sbu + stg * STG;
#pragma unroll
        for (int i = 0; i < 8; i++) {
            int idx  = i * 256 + t;
            int tile = idx >> 10;           // 0..1
            int rem  = idx & 1023;
            int row  = rem >> 3;            // 0..127
            int seg  = rem & 7;             // 0..7 (16B units)
            const __half* src = srcs[tile] + (size_t)row * KTOT + k0 + seg * 8;
            uint32_t dst = sb + tile * 16384 + row * 128 + (((seg ^ (row & 7))) << 4);
            CP_ASYNC16(dst, src);
        }
        CP_COMMIT();
    };

    float acc[4][4][4];
#pragma unroll
    for (int i = 0; i < 4; i++)
#pragma unroll
        for (int j = 0; j < 4; j++)
#pragma unroll
            for (int k = 0; k < 4; k++) acc[i][j][k] = 0.f;

    load_stage(0, 0);
    load_stage(1, 1);

    const int a_m = wm * 64 + (lane & 15);                            // + mf*16
    const int b_n = wn * 32 + ((lane >> 3) & 1) * 8 + (lane & 7);     // + p*16
    const int k8l = lane >> 4;                                        // k8 half

    int stg = 0;
    for (int c = 0; c < NC; c++) {
        CP_WAIT1();
        __syncthreads();
        if (c + 2 < NC) load_stage(c + 2, (c + 2) % 3);

        uint32_t sb = sbu + stg * STG;
#pragma unroll
        for (int ks = 0; ks < 4; ks++) {     // four k16 steps in BK=64
            int seg = ks * 2 + k8l;
            uint32_t A[4][4], B[2][4];
#pragma unroll
            for (int mf = 0; mf < 4; mf++) {
                int m = a_m + mf * 16;
                LDSM_X4(A[mf], sb + m * 128 + ((seg ^ (m & 7)) << 4));
            }
#pragma unroll
            for (int p = 0; p < 2; p++) {
                int n = b_n + p * 16;
                LDSM_X4(B[p], sb + 16384 + n * 128 + ((seg ^ (n & 7)) << 4));
            }
#pragma unroll
            for (int mf = 0; mf < 4; mf++) {
#pragma unroll
                for (int p = 0; p < 2; p++) {
                    MMA_F16(acc[mf][2 * p + 0], A[mf], B[p][0], B[p][2]);
                    MMA_F16(acc[mf][2 * p + 1], A[mf], B[p][1], B[p][3]);
                }
            }
        }
        __syncthreads();
        stg = (stg + 1 == 3) ? 0 : stg + 1;
    }

    // ---- epilogue --------------------------------------------------------------
    const int g = lane >> 2, q = lane & 3;
    if (IS_G1) {
#pragma unroll
        for (int mf = 0; mf < 4; mf++) {
#pragma unroll
            for (int h = 0; h < 2; h++) {
                int slotrow = mt * 128 + wm * 64 + mf * 16 + g + h * 8;
                size_t rowbase = ((size_t)e * CAP + slotrow) * H_DIM;
#pragma unroll
                for (int nf = 0; nf < 4; nf++) {
                    int col = nt * 128 + wn * 32 + nf * 8 + q * 2;
                    float v0 = fmaxf(acc[mf][nf][2 * h + 0] + __ldg(&bias[e * NTOT + col]),     0.f);
                    float v1 = fmaxf(acc[mf][nf][2 * h + 1] + __ldg(&bias[e * NTOT + col + 1]), 0.f);
                    __half2 hh = __floats2half2_rn(v0, v1);
                    *reinterpret_cast<uint32_t*>(&g_h[rowbase + col]) =
                        *reinterpret_cast<uint32_t*>(&hh);
                }
            }
        }
    } else {
#pragma unroll
        for (int mf = 0; mf < 4; mf++) {
#pragma unroll
            for (int h = 0; h < 2; h++) {
                int slotrow = mt * 128 + wm * 64 + mf * 16 + g + h * 8;
                int token = g_slot[e * CAP + slotrow];
                if (token < 0) continue;
                float gt = g_gate[token];
                float* orow = out + (size_t)token * M_DIM;
#pragma unroll
                for (int nf = 0; nf < 4; nf++) {
                    int col = nt * 128 + wn * 32 + nf * 8 + q * 2;
                    float2 v;
                    v.x = (acc[mf][nf][2 * h + 0] + __ldg(&bias[e * NTOT + col]))     * gt;
                    v.y = (acc[mf][nf][2 * h + 1] + __ldg(&bias[e * NTOT + col + 1])) * gt;
                    *(float2*)(orow + col) = v;
                }
            }
        }
    }
}

// ---------------- launch --------------------------------------------------------
extern "C" void kernel_launch(void* const* d_in, const int* in_sizes, int n_in,
                              void* d_out, int out_size) {
    const float* hs = (const float*)d_in[0];
    const float* wg = (const float*)d_in[1];
    const float* w1 = (const float*)d_in[2];   // [E, M, H]
    const float* b1 = (const float*)d_in[3];
    const float* w2 = (const float*)d_in[4];   // [E, H, M]
    const float* b2 = (const float*)d_in[5];
    float* out = (float*)d_out;

    constexpr int SMEM_BYTES = 3 * 32768;
    cudaFuncSetAttribute(moe_gemm_f16<M_DIM, true>,
                         cudaFuncAttributeMaxDynamicSharedMemorySize, SMEM_BYTES);
    cudaFuncSetAttribute(moe_gemm_f16<H_DIM, false>,
                         cudaFuncAttributeMaxDynamicSharedMemorySize, SMEM_BYTES);

    __half *a_p, *h_p, *w1t_p, *w2t_p;
    cudaGetSymbolAddress((void**)&a_p,   g_a);
    cudaGetSymbolAddress((void**)&h_p,   g_h);
    cudaGetSymbolAddress((void**)&w1t_p, g_w1t);
    cudaGetSymbolAddress((void**)&w2t_p, g_w2t);

    gate_kernel<<<S_TOK / 8, 256>>>(hs, wg);
    scan_kernel<<<1, 256>>>();
    transpose_half_kernel<<<dim3(H_DIM / 32, M_DIM / 32, N_EXP), dim3(32, 8)>>>(
        w1, w1t_p, M_DIM, H_DIM);   // [E,M,H] -> [E,H,M]
    transpose_half_kernel<<<dim3(M_DIM / 32, H_DIM / 32, N_EXP), dim3(32, 8)>>>(
        w2, w2t_p, H_DIM, M_DIM);   // [E,H,M] -> [E,M,H]
    gather_half_kernel<<<N_EXP * CAP, 128>>>(hs);
    zero_out_kernel<<<(S_TOK * M_DIM) / (4 * 256), 256>>>((float4*)out);

    moe_gemm_f16<M_DIM, true><<<dim3(H_DIM / 128, CAP / 128, N_EXP), 256, SMEM_BYTES>>>(
        a_p, w1t_p, b1, nullptr);
    moe_gemm_f16<H_DIM, false><<<dim3(M_DIM / 128, CAP / 128, N_EXP), 256, SMEM_BYTES>>>(
        h_p, w2t_p, b2, out);

    if (out_size > S_TOK * M_DIM)
        laux_kernel<<<1, 256>>>(out + (size_t)S_TOK * M_DIM);
}

// round 6
// speedup vs baseline: 3.8950x; 1.1531x over previous
#include <cuda_runtime.h>
#include <cuda_bf16.h>
#include <cuda_fp16.h>
#include <cstdint>
#include <cstddef>

// Problem constants
#define S_TOK 8192
#define M_DIM 512
#define H_DIM 1024
#define N_EXP 8
#define CAP   1024

// ---------------- portable PTX helpers (sm_103 baseline) ------------------------
__device__ __forceinline__ uint32_t smem_to_u32(const void* p) {
    uint32_t a;
    asm("{ .reg .u64 t; cvta.to.shared.u64 t, %1; cvt.u32.u64 %0, t; }" : "=r"(a) : "l"(p));
    return a;
}
#define CP_ASYNC16(dst, src) \
    asm volatile("cp.async.cg.shared.global [%0], [%1], 16;" :: "r"(dst), "l"(src))
#define CP_COMMIT() asm volatile("cp.async.commit_group;" ::: "memory")
#define CP_WAIT1()  asm volatile("cp.async.wait_group 1;" ::: "memory")
#define CP_WAIT0()  asm volatile("cp.async.wait_group 0;" ::: "memory")
#define LDSM_X4(r, addr) \
    asm volatile("ldmatrix.sync.aligned.m8n8.x4.shared.b16 {%0,%1,%2,%3}, [%4];" \
        : "=r"((r)[0]), "=r"((r)[1]), "=r"((r)[2]), "=r"((r)[3]) : "r"(addr))
#define MMA_F16(c, a, b0, b1) \
    asm volatile("mma.sync.aligned.m16n8k16.row.col.f32.f16.f16.f32 " \
        "{%0,%1,%2,%3}, {%4,%5,%6,%7}, {%8,%9}, {%0,%1,%2,%3};" \
        : "+f"((c)[0]), "+f"((c)[1]), "+f"((c)[2]), "+f"((c)[3]) \
        : "r"((a)[0]), "r"((a)[1]), "r"((a)[2]), "r"((a)[3]), "r"(b0), "r"(b1))

// ---------------- device scratch ------------------------------------------------
__device__ __half g_a[(size_t)N_EXP * CAP * M_DIM];            // gathered tokens fp16
__device__ __half g_h[(size_t)N_EXP * CAP * H_DIM];            // hidden fp16
__device__ __half g_w1t[(size_t)N_EXP * H_DIM * M_DIM];        // w1^T fp16 [E,H,M]
__device__ __half g_w2t[(size_t)N_EXP * M_DIM * H_DIM];        // w2^T fp16 [E,M,H]
__device__ float g_gates[(size_t)S_TOK * N_EXP];
__device__ float g_gate[S_TOK];
__device__ int   g_expert[S_TOK];
__device__ int   g_loc[S_TOK];
__device__ int   g_slot[N_EXP * CAP];
__device__ int   g_kept[N_EXP];

// ---------------- 1) gating -----------------------------------------------------
__global__ void gate_kernel(const float* __restrict__ feats, const float* __restrict__ wg) {
    __shared__ float wgT[N_EXP * M_DIM];
    int tid = threadIdx.x;
    for (int i = tid; i < N_EXP * M_DIM; i += 256) {
        int m = i & (M_DIM - 1);
        int e = i >> 9;
        wgT[e * M_DIM + m] = wg[m * N_EXP + e];
    }
    __syncthreads();
    int warp = tid >> 5, lane = tid & 31;
    int s = blockIdx.x * 8 + warp;
    const float* frow = feats + (size_t)s * M_DIM;
    float x[16];
#pragma unroll
    for (int j = 0; j < 16; j++) x[j] = frow[lane + 32 * j];
    float logit[N_EXP];
#pragma unroll
    for (int e = 0; e < N_EXP; e++) {
        const float* w = wgT + e * M_DIM;
        float acc = 0.f;
#pragma unroll
        for (int j = 0; j < 16; j++) acc += x[j] * w[lane + 32 * j];
#pragma unroll
        for (int off = 16; off > 0; off >>= 1)
            acc += __shfl_down_sync(0xffffffffu, acc, off);
        logit[e] = acc;
    }
    if (lane == 0) {
        float mx = logit[0]; int am = 0;
#pragma unroll
        for (int e = 1; e < N_EXP; e++)
            if (logit[e] > mx) { mx = logit[e]; am = e; }
        float ex[N_EXP]; float se = 0.f;
#pragma unroll
        for (int e = 0; e < N_EXP; e++) { ex[e] = expf(logit[e] - mx); se += ex[e]; }
        float inv = 1.f / se;
#pragma unroll
        for (int e = 0; e < N_EXP; e++) g_gates[(size_t)s * N_EXP + e] = ex[e] * inv;
        g_expert[s] = am;
        g_gate[s]   = ex[am] * inv;
    }
}

// ---------------- 2) capacity scan (smem-prefetched expert ids) -----------------
__global__ void scan_kernel() {
    __shared__ int sexp[S_TOK];           // 32KB
    __shared__ int base[N_EXP];
    __shared__ int wcnt[N_EXP][8];
    int tid = threadIdx.x;
    // prefetch all expert assignments (coalesced, overlapped across warps)
    for (int i = tid; i < S_TOK; i += 256) sexp[i] = g_expert[i];
    for (int i = tid; i < N_EXP * CAP; i += 256) g_slot[i] = -1;
    if (tid < N_EXP) base[tid] = 0;
    __syncthreads();
    int warp = tid >> 5, lane = tid & 31;
    unsigned ltmask = (lane == 0) ? 0u : (0xffffffffu >> (32 - lane));
    for (int tile = 0; tile < S_TOK / 256; tile++) {
        int s = tile * 256 + tid;
        int e = sexp[s];
        int myrank = 0;
#pragma unroll
        for (int eq = 0; eq < N_EXP; eq++) {
            unsigned bal = __ballot_sync(0xffffffffu, e == eq);
            if (e == eq) myrank = __popc(bal & ltmask);
            if (lane == 0) wcnt[eq][warp] = __popc(bal);
        }
        __syncthreads();
        int off = base[e];
        for (int w = 0; w < warp; w++) off += wcnt[e][w];
        int loc = off + myrank;
        g_loc[s] = loc;
        if (loc < CAP) g_slot[e * CAP + loc] = s;
        __syncthreads();
        if (tid < N_EXP) {
            int tot = 0;
#pragma unroll
            for (int w = 0; w < 8; w++) tot += wcnt[tid][w];
            base[tid] += tot;
        }
        __syncthreads();
    }
    if (tid < N_EXP) g_kept[tid] = min(base[tid], CAP);
}

// ---------------- 3) l_aux ------------------------------------------------------
__global__ void laux_kernel(float* __restrict__ out_laux) {
    __shared__ float partial[256];
    float w[N_EXP];
#pragma unroll
    for (int e = 0; e < N_EXP; e++) w[e] = (float)g_kept[e];
    float acc = 0.f;
    for (int s = threadIdx.x; s < S_TOK; s += 256) {
#pragma unroll
        for (int e = 0; e < N_EXP; e++) acc += g_gates[(size_t)s * N_EXP + e] * w[e];
    }
    partial[threadIdx.x] = acc;
    __syncthreads();
    for (int st = 128; st > 0; st >>= 1) {
        if (threadIdx.x < st) partial[threadIdx.x] += partial[threadIdx.x + st];
        __syncthreads();
    }
    if (threadIdx.x == 0)
        *out_laux = partial[0] * (float)N_EXP / ((float)S_TOK * (float)S_TOK);
}

// ---------------- 4) gather tokens -> fp16 A ------------------------------------
__global__ void gather_half_kernel(const float* __restrict__ feats) {
    int b = blockIdx.x;
    int tid = threadIdx.x;   // 128 threads x float4 = 512
    int token = g_slot[b];
    float4 v = make_float4(0.f, 0.f, 0.f, 0.f);
    if (token >= 0) v = ((const float4*)(feats + (size_t)token * M_DIM))[tid];
    __half2 h01 = __floats2half2_rn(v.x, v.y);
    __half2 h23 = __floats2half2_rn(v.z, v.w);
    uint2 hv;
    hv.x = *reinterpret_cast<uint32_t*>(&h01);
    hv.y = *reinterpret_cast<uint32_t*>(&h23);
    ((uint2*)(g_a + (size_t)b * M_DIM))[tid] = hv;
}

// ---------------- 5) weight transpose -> fp16 (half2 stores) --------------------
__global__ void transpose_half_kernel(const float* __restrict__ in,
                                      __half* __restrict__ outw, int R, int C) {
    __shared__ float t[32][33];
    int e = blockIdx.z;
    int r0 = blockIdx.y * 32, c0 = blockIdx.x * 32;
    const float* ine = in + (size_t)e * R * C;
    int tid = threadIdx.y * 32 + threadIdx.x;
#pragma unroll
    for (int i = 0; i < 4; i++)
        t[threadIdx.y + i * 8][threadIdx.x] =
            ine[(size_t)(r0 + threadIdx.y + i * 8) * C + c0 + threadIdx.x];
    __syncthreads();
    __half* oe = outw + (size_t)e * R * C;
#pragma unroll
    for (int it = 0; it < 2; it++) {
        int idx = it * 256 + tid;        // 0..511
        int ci  = idx >> 4;              // 0..31 -> output row (old col)
        int rp  = (idx & 15) * 2;        // 0..30 -> output col pair (old rows)
        __half2 v = __floats2half2_rn(t[rp][ci], t[rp + 1][ci]);
        *(__half2*)(oe + (size_t)(c0 + ci) * R + r0 + rp) = v;
    }
}

// ---------------- 6) zero output ------------------------------------------------
__global__ void zero_out_kernel(float4* __restrict__ out) {
    out[(size_t)blockIdx.x * 256 + threadIdx.x] = make_float4(0.f, 0.f, 0.f, 0.f);
}

// ---------------- 7) single-pass fp16 GEMM via mma.sync -------------------------
// CTA tile 128x128, BK=64, 2-stage cp.async pipeline, 2 CTAs/SM.
// Stage: A(16KB) + B(16KB); 128B rows (64 fp16), swizzle seg ^= row&7.
// 8 warps as 2(m) x 4(n); warp tile 64x32; per k16: 4mf x 2p x 2 = 16 MMAs.
template <int KTOT, bool IS_G1>
__global__ void __launch_bounds__(256, 2)
moe_gemm_f16(const __half* __restrict__ a_in, const __half* __restrict__ b_in,
             const float* __restrict__ bias, float* __restrict__ out) {
    constexpr int NTOT = IS_G1 ? H_DIM : M_DIM;
    constexpr int BK = 64;
    constexpr int NC = KTOT / BK;
    constexpr int STG = 32768;
    extern __shared__ __align__(1024) char smem[];
    const uint32_t sbu = smem_to_u32(smem);

    const int t = threadIdx.x;
    const int lane = t & 31, wid = t >> 5;
    const int wm = wid >> 2, wn = wid & 3;
    const int e = blockIdx.z, mt = blockIdx.y, nt = blockIdx.x;

    const __half* srcs[2] = {
        a_in + ((size_t)e * CAP  + mt * 128) * KTOT,
        b_in + ((size_t)e * NTOT + nt * 128) * KTOT};

    // ---- async stage loader: 8 x 16B per thread (2 tiles x 16KB) ---------------
    auto load_stage = [&](int c, int stg) {
        int k0 = c * BK;
        uint32_t sb = sbu + stg * STG;
#pragma unroll
        for (int i = 0; i < 8; i++) {
            int idx  = i * 256 + t;
            int tile = idx >> 10;           // 0..1
            int rem  = idx & 1023;
            int row  = rem >> 3;            // 0..127
            int seg  = rem & 7;             // 0..7 (16B units)
            const __half* src = srcs[tile] + (size_t)row * KTOT + k0 + seg * 8;
            uint32_t dst = sb + tile * 16384 + row * 128 + (((seg ^ (row & 7))) << 4);
            CP_ASYNC16(dst, src);
        }
        CP_COMMIT();
    };

    float acc[4][4][4];
#pragma unroll
    for (int i = 0; i < 4; i++)
#pragma unroll
        for (int j = 0; j < 4; j++)
#pragma unroll
            for (int k = 0; k < 4; k++) acc[i][j][k] = 0.f;

    load_stage(0, 0);
    load_stage(1, 1);

    const int a_m = wm * 64 + (lane & 15);                            // + mf*16
    const int b_n = wn * 32 + ((lane >> 3) & 1) * 8 + (lane & 7);     // + p*16
    const int k8l = lane >> 4;                                        // k8 half

    int stg = 0;
    for (int c = 0; c < NC; c++) {
        // group c must be complete; at the last iteration no younger group
        // may remain outstanding (wait_group 1 would leave it in flight).
        if (c == NC - 1) { CP_WAIT0(); } else { CP_WAIT1(); }
        __syncthreads();

        uint32_t sb = sbu + stg * STG;
#pragma unroll
        for (int ks = 0; ks < 4; ks++) {     // four k16 steps in BK=64
            int seg = ks * 2 + k8l;
            uint32_t A[4][4], B[2][4];
#pragma unroll
            for (int mf = 0; mf < 4; mf++) {
                int m = a_m + mf * 16;
                LDSM_X4(A[mf], sb + m * 128 + ((seg ^ (m & 7)) << 4));
            }
#pragma unroll
            for (int p = 0; p < 2; p++) {
                int n = b_n + p * 16;
                LDSM_X4(B[p], sb + 16384 + n * 128 + ((seg ^ (n & 7)) << 4));
            }
#pragma unroll
            for (int mf = 0; mf < 4; mf++) {
#pragma unroll
                for (int p = 0; p < 2; p++) {
                    MMA_F16(acc[mf][2 * p + 0], A[mf], B[p][0], B[p][2]);
                    MMA_F16(acc[mf][2 * p + 1], A[mf], B[p][1], B[p][3]);
                }
            }
        }
        __syncthreads();
        if (c + 2 < NC) load_stage(c + 2, stg);   // refill the buffer just consumed
        stg ^= 1;
    }

    // ---- epilogue --------------------------------------------------------------
    const int g = lane >> 2, q = lane & 3;
    if (IS_G1) {
#pragma unroll
        for (int mf = 0; mf < 4; mf++) {
#pragma unroll
            for (int h = 0; h < 2; h++) {
                int slotrow = mt * 128 + wm * 64 + mf * 16 + g + h * 8;
                size_t rowbase = ((size_t)e * CAP + slotrow) * H_DIM;
#pragma unroll
                for (int nf = 0; nf < 4; nf++) {
                    int col = nt * 128 + wn * 32 + nf * 8 + q * 2;
                    float v0 = fmaxf(acc[mf][nf][2 * h + 0] + __ldg(&bias[e * NTOT + col]),     0.f);
                    float v1 = fmaxf(acc[mf][nf][2 * h + 1] + __ldg(&bias[e * NTOT + col + 1]), 0.f);
                    __half2 hh = __floats2half2_rn(v0, v1);
                    *reinterpret_cast<uint32_t*>(&g_h[rowbase + col]) =
                        *reinterpret_cast<uint32_t*>(&hh);
                }
            }
        }
    } else {
#pragma unroll
        for (int mf = 0; mf < 4; mf++) {
#pragma unroll
            for (int h = 0; h < 2; h++) {
                int slotrow = mt * 128 + wm * 64 + mf * 16 + g + h * 8;
                int token = g_slot[e * CAP + slotrow];
                if (token < 0) continue;
                float gt = g_gate[token];
                float* orow = out + (size_t)token * M_DIM;
#pragma unroll
                for (int nf = 0; nf < 4; nf++) {
                    int col = nt * 128 + wn * 32 + nf * 8 + q * 2;
                    float2 v;
                    v.x = (acc[mf][nf][2 * h + 0] + __ldg(&bias[e * NTOT + col]))     * gt;
                    v.y = (acc[mf][nf][2 * h + 1] + __ldg(&bias[e * NTOT + col + 1])) * gt;
                    *(float2*)(orow + col) = v;
                }
            }
        }
    }
}

// ---------------- launch --------------------------------------------------------
extern "C" void kernel_launch(void* const* d_in, const int* in_sizes, int n_in,
                              void* d_out, int out_size) {
    const float* hs = (const float*)d_in[0];
    const float* wg = (const float*)d_in[1];
    const float* w1 = (const float*)d_in[2];   // [E, M, H]
    const float* b1 = (const float*)d_in[3];
    const float* w2 = (const float*)d_in[4];   // [E, H, M]
    const float* b2 = (const float*)d_in[5];
    float* out = (float*)d_out;

    constexpr int SMEM_BYTES = 2 * 32768;
    cudaFuncSetAttribute(moe_gemm_f16<M_DIM, true>,
                         cudaFuncAttributeMaxDynamicSharedMemorySize, SMEM_BYTES);
    cudaFuncSetAttribute(moe_gemm_f16<H_DIM, false>,
                         cudaFuncAttributeMaxDynamicSharedMemorySize, SMEM_BYTES);

    __half *a_p, *h_p, *w1t_p, *w2t_p;
    cudaGetSymbolAddress((void**)&a_p,   g_a);
    cudaGetSymbolAddress((void**)&h_p,   g_h);
    cudaGetSymbolAddress((void**)&w1t_p, g_w1t);
    cudaGetSymbolAddress((void**)&w2t_p, g_w2t);

    gate_kernel<<<S_TOK / 8, 256>>>(hs, wg);
    scan_kernel<<<1, 256>>>();
    transpose_half_kernel<<<dim3(H_DIM / 32, M_DIM / 32, N_EXP), dim3(32, 8)>>>(
        w1, w1t_p, M_DIM, H_DIM);   // [E,M,H] -> [E,H,M]
    transpose_half_kernel<<<dim3(M_DIM / 32, H_DIM / 32, N_EXP), dim3(32, 8)>>>(
        w2, w2t_p, H_DIM, M_DIM);   // [E,H,M] -> [E,M,H]
    gather_half_kernel<<<N_EXP * CAP, 128>>>(hs);
    zero_out_kernel<<<(S_TOK * M_DIM) / (4 * 256), 256>>>((float4*)out);

    moe_gemm_f16<M_DIM, true><<<dim3(H_DIM / 128, CAP / 128, N_EXP), 256, SMEM_BYTES>>>(
        a_p, w1t_p, b1, nullptr);
    moe_gemm_f16<H_DIM, false><<<dim3(M_DIM / 128, CAP / 128, N_EXP), 256, SMEM_BYTES>>>(
        h_p, w2t_p, b2, out);

    if (out_size > S_TOK * M_DIM)
        laux_kernel<<<1, 256>>>(out + (size_t)S_TOK * M_DIM);
}

// round 9
// speedup vs baseline: 3.9547x; 1.0153x over previous
#include <cuda_runtime.h>
#include <cuda_bf16.h>
#include <cuda_fp16.h>
#include <cstdint>
#include <cstddef>

// Problem constants
#define S_TOK 8192
#define M_DIM 512
#define H_DIM 1024
#define N_EXP 8
#define CAP   1024

// ---------------- portable PTX helpers (sm_103 baseline) ------------------------
__device__ __forceinline__ uint32_t smem_to_u32(const void* p) {
    uint32_t a;
    asm("{ .reg .u64 t; cvta.to.shared.u64 t, %1; cvt.u32.u64 %0, t; }" : "=r"(a) : "l"(p));
    return a;
}
#define CP_ASYNC16(dst, src) \
    asm volatile("cp.async.cg.shared.global [%0], [%1], 16;" :: "r"(dst), "l"(src))
#define CP_COMMIT() asm volatile("cp.async.commit_group;" ::: "memory")
#define CP_WAIT1()  asm volatile("cp.async.wait_group 1;" ::: "memory")
#define CP_WAIT0()  asm volatile("cp.async.wait_group 0;" ::: "memory")
#define LDSM_X4(r, addr) \
    asm volatile("ldmatrix.sync.aligned.m8n8.x4.shared.b16 {%0,%1,%2,%3}, [%4];" \
        : "=r"((r)[0]), "=r"((r)[1]), "=r"((r)[2]), "=r"((r)[3]) : "r"(addr))
#define MMA_F16(c, a, b0, b1) \
    asm volatile("mma.sync.aligned.m16n8k16.row.col.f32.f16.f16.f32 " \
        "{%0,%1,%2,%3}, {%4,%5,%6,%7}, {%8,%9}, {%0,%1,%2,%3};" \
        : "+f"((c)[0]), "+f"((c)[1]), "+f"((c)[2]), "+f"((c)[3]) \
        : "r"((a)[0]), "r"((a)[1]), "r"((a)[2]), "r"((a)[3]), "r"(b0), "r"(b1))

// ---------------- device scratch ------------------------------------------------
__device__ __half g_a[(size_t)N_EXP * CAP * M_DIM];            // gathered tokens fp16
__device__ __half g_h[(size_t)N_EXP * CAP * H_DIM];            // hidden fp16
__device__ __half g_w1t[(size_t)N_EXP * H_DIM * M_DIM];        // w1^T fp16 [E,H,M]
__device__ __half g_w2t[(size_t)N_EXP * M_DIM * H_DIM];        // w2^T fp16 [E,M,H]
__device__ float g_gates[(size_t)S_TOK * N_EXP];
__device__ float g_gate[S_TOK];
__device__ int   g_expert[S_TOK];
__device__ int   g_loc[S_TOK];
__device__ int   g_slot[N_EXP * CAP];
__device__ int   g_kept[N_EXP];

// ---------------- 1) gating -----------------------------------------------------
__global__ void gate_kernel(const float* __restrict__ feats, const float* __restrict__ wg) {
    __shared__ float wgT[N_EXP * M_DIM];
    int tid = threadIdx.x;
    for (int i = tid; i < N_EXP * M_DIM; i += 256) {
        int m = i & (M_DIM - 1);
        int e = i >> 9;
        wgT[e * M_DIM + m] = wg[m * N_EXP + e];
    }
    __syncthreads();
    int warp = tid >> 5, lane = tid & 31;
    int s = blockIdx.x * 8 + warp;
    const float* frow = feats + (size_t)s * M_DIM;
    float x[16];
#pragma unroll
    for (int j = 0; j < 16; j++) x[j] = frow[lane + 32 * j];
    float logit[N_EXP];
#pragma unroll
    for (int e = 0; e < N_EXP; e++) {
        const float* w = wgT + e * M_DIM;
        float acc = 0.f;
#pragma unroll
        for (int j = 0; j < 16; j++) acc += x[j] * w[lane + 32 * j];
#pragma unroll
        for (int off = 16; off > 0; off >>= 1)
            acc += __shfl_down_sync(0xffffffffu, acc, off);
        logit[e] = acc;
    }
    if (lane == 0) {
        float mx = logit[0]; int am = 0;
#pragma unroll
        for (int e = 1; e < N_EXP; e++)
            if (logit[e] > mx) { mx = logit[e]; am = e; }
        float ex[N_EXP]; float se = 0.f;
#pragma unroll
        for (int e = 0; e < N_EXP; e++) { ex[e] = expf(logit[e] - mx); se += ex[e]; }
        float inv = 1.f / se;
#pragma unroll
        for (int e = 0; e < N_EXP; e++) g_gates[(size_t)s * N_EXP + e] = ex[e] * inv;
        g_expert[s] = am;
        g_gate[s]   = ex[am] * inv;
    }
}

// ---------------- 2) capacity scan (smem-prefetched expert ids) -----------------
__global__ void scan_kernel() {
    __shared__ int sexp[S_TOK];           // 32KB
    __shared__ int base[N_EXP];
    __shared__ int wcnt[N_EXP][8];
    int tid = threadIdx.x;
    for (int i = tid; i < S_TOK; i += 256) sexp[i] = g_expert[i];
    for (int i = tid; i < N_EXP * CAP; i += 256) g_slot[i] = -1;
    if (tid < N_EXP) base[tid] = 0;
    __syncthreads();
    int warp = tid >> 5, lane = tid & 31;
    unsigned ltmask = (lane == 0) ? 0u : (0xffffffffu >> (32 - lane));
    for (int tile = 0; tile < S_TOK / 256; tile++) {
        int s = tile * 256 + tid;
        int e = sexp[s];
        int myrank = 0;
#pragma unroll
        for (int eq = 0; eq < N_EXP; eq++) {
            unsigned bal = __ballot_sync(0xffffffffu, e == eq);
            if (e == eq) myrank = __popc(bal & ltmask);
            if (lane == 0) wcnt[eq][warp] = __popc(bal);
        }
        __syncthreads();
        int off = base[e];
        for (int w = 0; w < warp; w++) off += wcnt[e][w];
        int loc = off + myrank;
        g_loc[s] = loc;
        if (loc < CAP) g_slot[e * CAP + loc] = s;
        __syncthreads();
        if (tid < N_EXP) {
            int tot = 0;
#pragma unroll
            for (int w = 0; w < 8; w++) tot += wcnt[tid][w];
            base[tid] += tot;
        }
        __syncthreads();
    }
    if (tid < N_EXP) g_kept[tid] = min(base[tid], CAP);
}

// ---------------- 3) l_aux ------------------------------------------------------
__global__ void laux_kernel(float* __restrict__ out_laux) {
    __shared__ float partial[256];
    float w[N_EXP];
#pragma unroll
    for (int e = 0; e < N_EXP; e++) w[e] = (float)g_kept[e];
    float acc = 0.f;
    for (int s = threadIdx.x; s < S_TOK; s += 256) {
#pragma unroll
        for (int e = 0; e < N_EXP; e++) acc += g_gates[(size_t)s * N_EXP + e] * w[e];
    }
    partial[threadIdx.x] = acc;
    __syncthreads();
    for (int st = 128; st > 0; st >>= 1) {
        if (threadIdx.x < st) partial[threadIdx.x] += partial[threadIdx.x + st];
        __syncthreads();
    }
    if (threadIdx.x == 0)
        *out_laux = partial[0] * (float)N_EXP / ((float)S_TOK * (float)S_TOK);
}

// ---------------- 4) gather tokens -> fp16 A ------------------------------------
__global__ void gather_half_kernel(const float* __restrict__ feats) {
    int b = blockIdx.x;
    int tid = threadIdx.x;   // 128 threads x float4 = 512
    int token = g_slot[b];
    float4 v = make_float4(0.f, 0.f, 0.f, 0.f);
    if (token >= 0) v = ((const float4*)(feats + (size_t)token * M_DIM))[tid];
    __half2 h01 = __floats2half2_rn(v.x, v.y);
    __half2 h23 = __floats2half2_rn(v.z, v.w);
    uint2 hv;
    hv.x = *reinterpret_cast<uint32_t*>(&h01);
    hv.y = *reinterpret_cast<uint32_t*>(&h23);
    ((uint2*)(g_a + (size_t)b * M_DIM))[tid] = hv;
}

// ---------------- 5) weight transpose -> fp16 (half2 stores) --------------------
__global__ void transpose_half_kernel(const float* __restrict__ in,
                                      __half* __restrict__ outw, int R, int C) {
    __shared__ float t[32][33];
    int e = blockIdx.z;
    int r0 = blockIdx.y * 32, c0 = blockIdx.x * 32;
    const float* ine = in + (size_t)e * R * C;
    int tid = threadIdx.y * 32 + threadIdx.x;
#pragma unroll
    for (int i = 0; i < 4; i++)
        t[threadIdx.y + i * 8][threadIdx.x] =
            ine[(size_t)(r0 + threadIdx.y + i * 8) * C + c0 + threadIdx.x];
    __syncthreads();
    __half* oe = outw + (size_t)e * R * C;
#pragma unroll
    for (int it = 0; it < 2; it++) {
        int idx = it * 256 + tid;        // 0..511
        int ci  = idx >> 4;              // 0..31 -> output row (old col)
        int rp  = (idx & 15) * 2;        // 0..30 -> output col pair (old rows)
        __half2 v = __floats2half2_rn(t[rp][ci], t[rp + 1][ci]);
        *(__half2*)(oe + (size_t)(c0 + ci) * R + r0 + rp) = v;
    }
}

// ---------------- 6) zero only dropped-token rows -------------------------------
// GEMM2's epilogue scatter writes every kept token's row; only overflow-dropped
// tokens (loc >= CAP) need explicit zeros.
__global__ void zero_dropped_kernel(float* __restrict__ out) {
    int s = blockIdx.x * 8 + (threadIdx.x >> 5);
    if (g_loc[s] < CAP) return;
    int lane = threadIdx.x & 31;
    float4* row = (float4*)(out + (size_t)s * M_DIM);
#pragma unroll
    for (int i = 0; i < 4; i++)
        row[lane + 32 * i] = make_float4(0.f, 0.f, 0.f, 0.f);
}

// ---------------- 7) single-pass fp16 GEMM via mma.sync -------------------------
// CTA tile 128x128, BK=64, 2-stage cp.async pipeline, 128 threads, 2 CTAs/SM.
// 4 warps as 2(m) x 2(n); warp tile 64x64 -> halves per-FLOP LDSM traffic vs 64x32.
// Stage: A(16KB) + B(16KB); 128B rows (64 fp16), swizzle seg ^= row&7.
template <int KTOT, bool IS_G1>
__global__ void __launch_bounds__(128, 2)
moe_gemm_f16(const __half* __restrict__ a_in, const __half* __restrict__ b_in,
             const float* __restrict__ bias, float* __restrict__ out) {
    constexpr int NTOT = IS_G1 ? H_DIM : M_DIM;
    constexpr int BK = 64;
    constexpr int NC = KTOT / BK;
    constexpr int STG = 32768;
    extern __shared__ __align__(1024) char smem[];
    const uint32_t sbu = smem_to_u32(smem);

    const int t = threadIdx.x;
    const int lane = t & 31, wid = t >> 5;
    const int wm = wid >> 1, wn = wid & 1;
    const int e = blockIdx.z, mt = blockIdx.y, nt = blockIdx.x;

    const __half* srcs[2] = {
        a_in + ((size_t)e * CAP  + mt * 128) * KTOT,
        b_in + ((size_t)e * NTOT + nt * 128) * KTOT};

    // ---- async stage loader: 16 x 16B per thread (2 tiles x 16KB) --------------
    auto load_stage = [&](int c, int stg) {
        int k0 = c * BK;
        uint32_t sb = sbu + stg * STG;
#pragma unroll
        for (int i = 0; i < 16; i++) {
            int idx  = i * 128 + t;
            int tile = idx >> 10;           // 0..1
            int rem  = idx & 1023;
            int row  = rem >> 3;            // 0..127
            int seg  = rem & 7;             // 0..7 (16B units)
            const __half* src = srcs[tile] + (size_t)row * KTOT + k0 + seg * 8;
            uint32_t dst = sb + tile * 16384 + row * 128 + (((seg ^ (row & 7))) << 4);
            CP_ASYNC16(dst, src);
        }
        CP_COMMIT();
    };

    float acc[4][8][4];
#pragma unroll
    for (int i = 0; i < 4; i++)
#pragma unroll
        for (int j = 0; j < 8; j++)
#pragma unroll
            for (int k = 0; k < 4; k++) acc[i][j][k] = 0.f;

    load_stage(0, 0);
    load_stage(1, 1);

    const int a_m = wm * 64 + (lane & 15);                            // + mf*16
    const int b_n = wn * 64 + ((lane >> 3) & 1) * 8 + (lane & 7);     // + p*16
    const int k8l = lane >> 4;                                        // k8 half

    int stg = 0;
    for (int c = 0; c < NC; c++) {
        if (c == NC - 1) { CP_WAIT0(); } else { CP_WAIT1(); }
        __syncthreads();

        uint32_t sb = sbu + stg * STG;
#pragma unroll
        for (int ks = 0; ks < 4; ks++) {     // four k16 steps in BK=64
            int seg = ks * 2 + k8l;
            uint32_t A[4][4], B[4][4];
#pragma unroll
            for (int mf = 0; mf < 4; mf++) {
                int m = a_m + mf * 16;
                LDSM_X4(A[mf], sb + m * 128 + ((seg ^ (m & 7)) << 4));
            }
#pragma unroll
            for (int p = 0; p < 4; p++) {
                int n = b_n + p * 16;
                LDSM_X4(B[p], sb + 16384 + n * 128 + ((seg ^ (n & 7)) << 4));
            }
#pragma unroll
            for (int mf = 0; mf < 4; mf++) {
#pragma unroll
                for (int p = 0; p < 4; p++) {
                    MMA_F16(acc[mf][2 * p + 0], A[mf], B[p][0], B[p][2]);
                    MMA_F16(acc[mf][2 * p + 1], A[mf], B[p][1], B[p][3]);
                }
            }
        }
        __syncthreads();
        if (c + 2 < NC) load_stage(c + 2, stg);   // refill the buffer just consumed
        stg ^= 1;
    }

    // ---- epilogue --------------------------------------------------------------
    const int g = lane >> 2, q = lane & 3;
    if (IS_G1) {
#pragma unroll
        for (int mf = 0; mf < 4; mf++) {
#pragma unroll
            for (int h = 0; h < 2; h++) {
                int slotrow = mt * 128 + wm * 64 + mf * 16 + g + h * 8;
                size_t rowbase = ((size_t)e * CAP + slotrow) * H_DIM;
#pragma unroll
                for (int nf = 0; nf < 8; nf++) {
                    int col = nt * 128 + wn * 64 + nf * 8 + q * 2;
                    float v0 = fmaxf(acc[mf][nf][2 * h + 0] + __ldg(&bias[e * NTOT + col]),     0.f);
                    float v1 = fmaxf(acc[mf][nf][2 * h + 1] + __ldg(&bias[e * NTOT + col + 1]), 0.f);
                    __half2 hh = __floats2half2_rn(v0, v1);
                    *reinterpret_cast<uint32_t*>(&g_h[rowbase + col]) =
                        *reinterpret_cast<uint32_t*>(&hh);
                }
            }
        }
    } else {
#pragma unroll
        for (int mf = 0; mf < 4; mf++) {
#pragma unroll
            for (int h = 0; h < 2; h++) {
                int slotrow = mt * 128 + wm * 64 + mf * 16 + g + h * 8;
                int token = g_slot[e * CAP + slotrow];
                if (token < 0) continue;
                float gt = g_gate[token];
                float* orow = out + (size_t)token * M_DIM;
#pragma unroll
                for (int nf = 0; nf < 8; nf++) {
                    int col = nt * 128 + wn * 64 + nf * 8 + q * 2;
                    float2 v;
                    v.x = (acc[mf][nf][2 * h + 0] + __ldg(&bias[e * NTOT + col]))     * gt;
                    v.y = (acc[mf][nf][2 * h + 1] + __ldg(&bias[e * NTOT + col + 1])) * gt;
                    *(float2*)(orow + col) = v;
                }
            }
        }
    }
}

// ---------------- launch --------------------------------------------------------
extern "C" void kernel_launch(void* const* d_in, const int* in_sizes, int n_in,
                              void* d_out, int out_size) {
    const float* hs = (const float*)d_in[0];
    const float* wg = (const float*)d_in[1];
    const float* w1 = (const float*)d_in[2];   // [E, M, H]
    const float* b1 = (const float*)d_in[3];
    const float* w2 = (const float*)d_in[4];   // [E, H, M]
    const float* b2 = (const float*)d_in[5];
    float* out = (float*)d_out;

    constexpr int SMEM_BYTES = 2 * 32768;
    cudaFuncSetAttribute(moe_gemm_f16<M_DIM, true>,
                         cudaFuncAttributeMaxDynamicSharedMemorySize, SMEM_BYTES);
    cudaFuncSetAttribute(moe_gemm_f16<H_DIM, false>,
                         cudaFuncAttributeMaxDynamicSharedMemorySize, SMEM_BYTES);

    __half *a_p, *h_p, *w1t_p, *w2t_p;
    cudaGetSymbolAddress((void**)&a_p,   g_a);
    cudaGetSymbolAddress((void**)&h_p,   g_h);
    cudaGetSymbolAddress((void**)&w1t_p, g_w1t);
    cudaGetSymbolAddress((void**)&w2t_p, g_w2t);

    gate_kernel<<<S_TOK / 8, 256>>>(hs, wg);
    scan_kernel<<<1, 256>>>();
    transpose_half_kernel<<<dim3(H_DIM / 32, M_DIM / 32, N_EXP), dim3(32, 8)>>>(
        w1, w1t_p, M_DIM, H_DIM);   // [E,M,H] -> [E,H,M]
    transpose_half_kernel<<<dim3(M_DIM / 32, H_DIM / 32, N_EXP), dim3(32, 8)>>>(
        w2, w2t_p, H_DIM, M_DIM);   // [E,H,M] -> [E,M,H]
    gather_half_kernel<<<N_EXP * CAP, 128>>>(hs);
    zero_dropped_kernel<<<S_TOK / 8, 256>>>(out);

    moe_gemm_f16<M_DIM, true><<<dim3(H_DIM / 128, CAP / 128, N_EXP), 128, SMEM_BYTES>>>(
        a_p, w1t_p, b1, nullptr);
    moe_gemm_f16<H_DIM, false><<<dim3(M_DIM / 128, CAP / 128, N_EXP), 128, SMEM_BYTES>>>(
        h_p, w2t_p, b2, out);

    if (out_size > S_TOK * M_DIM)
        laux_kernel<<<1, 256>>>(out + (size_t)S_TOK * M_DIM);
}

// round 10
// speedup vs baseline: 4.4969x; 1.1371x over previous
#include <cuda_runtime.h>
#include <cuda_bf16.h>
#include <cuda_fp16.h>
#include <cstdint>
#include <cstddef>

// Problem constants
#define S_TOK 8192
#define M_DIM 512
#define H_DIM 1024
#define N_EXP 8
#define CAP   1024

// ---------------- portable PTX helpers (sm_103 baseline) ------------------------
__device__ __forceinline__ uint32_t smem_to_u32(const void* p) {
    uint32_t a;
    asm("{ .reg .u64 t; cvta.to.shared.u64 t, %1; cvt.u32.u64 %0, t; }" : "=r"(a) : "l"(p));
    return a;
}
#define CP_ASYNC16(dst, src) \
    asm volatile("cp.async.cg.shared.global [%0], [%1], 16;" :: "r"(dst), "l"(src))
#define CP_COMMIT() asm volatile("cp.async.commit_group;" ::: "memory")
#define CP_WAIT1()  asm volatile("cp.async.wait_group 1;" ::: "memory")
#define CP_WAIT0()  asm volatile("cp.async.wait_group 0;" ::: "memory")
#define LDSM_X4(r, addr) \
    asm volatile("ldmatrix.sync.aligned.m8n8.x4.shared.b16 {%0,%1,%2,%3}, [%4];" \
        : "=r"((r)[0]), "=r"((r)[1]), "=r"((r)[2]), "=r"((r)[3]) : "r"(addr))
#define MMA_F16(c, a, b0, b1) \
    asm volatile("mma.sync.aligned.m16n8k16.row.col.f32.f16.f16.f32 " \
        "{%0,%1,%2,%3}, {%4,%5,%6,%7}, {%8,%9}, {%0,%1,%2,%3};" \
        : "+f"((c)[0]), "+f"((c)[1]), "+f"((c)[2]), "+f"((c)[3]) \
        : "r"((a)[0]), "r"((a)[1]), "r"((a)[2]), "r"((a)[3]), "r"(b0), "r"(b1))

// ---------------- device scratch ------------------------------------------------
__device__ __half g_a[(size_t)N_EXP * CAP * M_DIM];            // gathered tokens fp16
__device__ __half g_h[(size_t)N_EXP * CAP * H_DIM];            // hidden fp16
__device__ __half g_w1t[(size_t)N_EXP * H_DIM * M_DIM];        // w1^T fp16 [E,H,M]
__device__ __half g_w2t[(size_t)N_EXP * M_DIM * H_DIM];        // w2^T fp16 [E,M,H]
__device__ float g_gates[(size_t)S_TOK * N_EXP];
__device__ float g_gate[S_TOK];
__device__ int   g_expert[S_TOK];
__device__ int   g_loc[S_TOK];
__device__ int   g_slot[N_EXP * CAP];

// ---------------- 1) gating -----------------------------------------------------
__global__ void gate_kernel(const float* __restrict__ feats, const float* __restrict__ wg) {
    __shared__ float wgT[N_EXP * M_DIM];
    int tid = threadIdx.x;
    for (int i = tid; i < N_EXP * M_DIM; i += 256) {
        int m = i & (M_DIM - 1);
        int e = i >> 9;
        wgT[e * M_DIM + m] = wg[m * N_EXP + e];
    }
    __syncthreads();
    int warp = tid >> 5, lane = tid & 31;
    int s = blockIdx.x * 8 + warp;
    const float* frow = feats + (size_t)s * M_DIM;
    float x[16];
#pragma unroll
    for (int j = 0; j < 16; j++) x[j] = frow[lane + 32 * j];
    float logit[N_EXP];
#pragma unroll
    for (int e = 0; e < N_EXP; e++) {
        const float* w = wgT + e * M_DIM;
        float acc = 0.f;
#pragma unroll
        for (int j = 0; j < 16; j++) acc += x[j] * w[lane + 32 * j];
#pragma unroll
        for (int off = 16; off > 0; off >>= 1)
            acc += __shfl_down_sync(0xffffffffu, acc, off);
        logit[e] = acc;
    }
    if (lane == 0) {
        float mx = logit[0]; int am = 0;
#pragma unroll
        for (int e = 1; e < N_EXP; e++)
            if (logit[e] > mx) { mx = logit[e]; am = e; }
        float ex[N_EXP]; float se = 0.f;
#pragma unroll
        for (int e = 0; e < N_EXP; e++) { ex[e] = expf(logit[e] - mx); se += ex[e]; }
        float inv = 1.f / se;
#pragma unroll
        for (int e = 0; e < N_EXP; e++) g_gates[(size_t)s * N_EXP + e] = ex[e] * inv;
        g_expert[s] = am;
        g_gate[s]   = ex[am] * inv;
    }
}

// ---------------- 2) parallel capacity scan + fused l_aux -----------------------
// 1024 threads = 32 warps; warp w owns token block [w*256, w*256+256).
// Phase 1: per-warp-block expert counts (ballot, all warps parallel).
// Phase 2: exclusive prefix across warp-blocks per expert.
// Phase 3: parallel slot assignment with identical rank recomputation.
// Tail:    l_aux reduction using totals (fused; saves a launch).
__global__ void scan_kernel(float* __restrict__ laux_out, int write_laux) {
    __shared__ int sexp[S_TOK];          // 32KB
    __shared__ int cnt[32][N_EXP];       // per-warp-block counts
    __shared__ int off[32][N_EXP];       // exclusive prefix per block
    __shared__ int tot[N_EXP];           // totals per expert
    __shared__ float red[1024];
    int tid = threadIdx.x;
    int warp = tid >> 5, lane = tid & 31;
    unsigned ltmask = (lane == 0) ? 0u : (0xffffffffu >> (32 - lane));

    for (int i = tid; i < S_TOK; i += 1024) sexp[i] = g_expert[i];
    for (int i = tid; i < N_EXP * CAP; i += 1024) g_slot[i] = -1;
    __syncthreads();

    // Phase 1: counts
    {
        int run[N_EXP];
#pragma unroll
        for (int e = 0; e < N_EXP; e++) run[e] = 0;
#pragma unroll
        for (int it = 0; it < 8; it++) {
            int s = warp * 256 + it * 32 + lane;
            int e = sexp[s];
#pragma unroll
            for (int eq = 0; eq < N_EXP; eq++) {
                unsigned bal = __ballot_sync(0xffffffffu, e == eq);
                run[eq] += __popc(bal);
            }
        }
        if (lane < N_EXP) cnt[warp][lane] = run[lane];
    }
    __syncthreads();

    // Phase 2: exclusive prefix + totals (256 threads: (w,e) pairs)
    if (tid < 256) {
        int w = tid >> 3, e = tid & 7;
        int acc = 0;
        for (int wp = 0; wp < w; wp++) acc += cnt[wp][e];
        off[w][e] = acc;
        if (w == 31) tot[e] = acc + cnt[31][e];
    }
    __syncthreads();

    // Phase 3: assignment
    {
        int run[N_EXP];
#pragma unroll
        for (int e = 0; e < N_EXP; e++) run[e] = off[warp][e];
#pragma unroll
        for (int it = 0; it < 8; it++) {
            int s = warp * 256 + it * 32 + lane;
            int e = sexp[s];
            int myrank = 0;
            unsigned bals[N_EXP];
#pragma unroll
            for (int eq = 0; eq < N_EXP; eq++) {
                bals[eq] = __ballot_sync(0xffffffffu, e == eq);
                if (e == eq) myrank = __popc(bals[eq] & ltmask);
            }
            int loc = run[e] + myrank;
            g_loc[s] = loc;
            if (loc < CAP) g_slot[e * CAP + loc] = s;
#pragma unroll
            for (int eq = 0; eq < N_EXP; eq++) run[eq] += __popc(bals[eq]);
        }
    }

    // Fused l_aux
    if (!write_laux) return;
    float w[N_EXP];
#pragma unroll
    for (int e = 0; e < N_EXP; e++) w[e] = (float)min(tot[e], CAP);
    float acc = 0.f;
    for (int s = tid; s < S_TOK; s += 1024) {
        const float4* gp = (const float4*)(g_gates + (size_t)s * N_EXP);
        float4 a = gp[0], b = gp[1];
        acc += a.x * w[0] + a.y * w[1] + a.z * w[2] + a.w * w[3]
             + b.x * w[4] + b.y * w[5] + b.z * w[6] + b.w * w[7];
    }
    red[tid] = acc;
    __syncthreads();
    for (int st = 512; st > 0; st >>= 1) {
        if (tid < st) red[tid] += red[tid + st];
        __syncthreads();
    }
    if (tid == 0)
        *laux_out = red[0] * (float)N_EXP / ((float)S_TOK * (float)S_TOK);
}

// ---------------- 3) gather tokens -> fp16 A ------------------------------------
__global__ void gather_half_kernel(const float* __restrict__ feats) {
    int b = blockIdx.x;
    int tid = threadIdx.x;   // 128 threads x float4 = 512
    int token = g_slot[b];
    float4 v = make_float4(0.f, 0.f, 0.f, 0.f);
    if (token >= 0) v = ((const float4*)(feats + (size_t)token * M_DIM))[tid];
    __half2 h01 = __floats2half2_rn(v.x, v.y);
    __half2 h23 = __floats2half2_rn(v.z, v.w);
    uint2 hv;
    hv.x = *reinterpret_cast<uint32_t*>(&h01);
    hv.y = *reinterpret_cast<uint32_t*>(&h23);
    ((uint2*)(g_a + (size_t)b * M_DIM))[tid] = hv;
}

// ---------------- 4) weight transpose -> fp16 (half2 stores) --------------------
__global__ void transpose_half_kernel(const float* __restrict__ in,
                                      __half* __restrict__ outw, int R, int C) {
    __shared__ float t[32][33];
    int e = blockIdx.z;
    int r0 = blockIdx.y * 32, c0 = blockIdx.x * 32;
    const float* ine = in + (size_t)e * R * C;
    int tid = threadIdx.y * 32 + threadIdx.x;
#pragma unroll
    for (int i = 0; i < 4; i++)
        t[threadIdx.y + i * 8][threadIdx.x] =
            ine[(size_t)(r0 + threadIdx.y + i * 8) * C + c0 + threadIdx.x];
    __syncthreads();
    __half* oe = outw + (size_t)e * R * C;
#pragma unroll
    for (int it = 0; it < 2; it++) {
        int idx = it * 256 + tid;        // 0..511
        int ci  = idx >> 4;              // 0..31 -> output row (old col)
        int rp  = (idx & 15) * 2;        // 0..30 -> output col pair (old rows)
        __half2 v = __floats2half2_rn(t[rp][ci], t[rp + 1][ci]);
        *(__half2*)(oe + (size_t)(c0 + ci) * R + r0 + rp) = v;
    }
}

// ---------------- 5) zero only dropped-token rows -------------------------------
__global__ void zero_dropped_kernel(float* __restrict__ out) {
    int s = blockIdx.x * 8 + (threadIdx.x >> 5);
    if (g_loc[s] < CAP) return;
    int lane = threadIdx.x & 31;
    float4* row = (float4*)(out + (size_t)s * M_DIM);
#pragma unroll
    for (int i = 0; i < 4; i++)
        row[lane + 32 * i] = make_float4(0.f, 0.f, 0.f, 0.f);
}

// ---------------- 6) single-pass fp16 GEMM via mma.sync -------------------------
// CTA tile 128x128, BK=64, 3-stage cp.async pipeline, 128 threads, 2 CTAs/SM.
// 4 warps as 2(m) x 2(n); warp tile 64x64. One barrier per chunk; refill issued
// before the chunk's MMAs so copies overlap compute.
// Stage: A(16KB) + B(16KB); 128B rows (64 fp16), swizzle seg ^= row&7.
template <int KTOT, bool IS_G1>
__global__ void __launch_bounds__(128, 2)
moe_gemm_f16(const __half* __restrict__ a_in, const __half* __restrict__ b_in,
             const float* __restrict__ bias, float* __restrict__ out) {
    constexpr int NTOT = IS_G1 ? H_DIM : M_DIM;
    constexpr int BK = 64;
    constexpr int NC = KTOT / BK;
    constexpr int STG = 32768;
    extern __shared__ __align__(1024) char smem[];
    const uint32_t sbu = smem_to_u32(smem);

    const int t = threadIdx.x;
    const int lane = t & 31, wid = t >> 5;
    const int wm = wid >> 1, wn = wid & 1;
    const int e = blockIdx.z, mt = blockIdx.y, nt = blockIdx.x;

    const __half* srcs[2] = {
        a_in + ((size_t)e * CAP  + mt * 128) * KTOT,
        b_in + ((size_t)e * NTOT + nt * 128) * KTOT};

    // ---- async stage loader: 16 x 16B per thread (2 tiles x 16KB) --------------
    auto load_stage = [&](int c, int stg) {
        int k0 = c * BK;
        uint32_t sb = sbu + stg * STG;
#pragma unroll
        for (int i = 0; i < 16; i++) {
            int idx  = i * 128 + t;
            int tile = idx >> 10;           // 0..1
            int rem  = idx & 1023;
            int row  = rem >> 3;            // 0..127
            int seg  = rem & 7;             // 0..7 (16B units)
            const __half* src = srcs[tile] + (size_t)row * KTOT + k0 + seg * 8;
            uint32_t dst = sb + tile * 16384 + row * 128 + (((seg ^ (row & 7))) << 4);
            CP_ASYNC16(dst, src);
        }
        CP_COMMIT();
    };

    float acc[4][8][4];
#pragma unroll
    for (int i = 0; i < 4; i++)
#pragma unroll
        for (int j = 0; j < 8; j++)
#pragma unroll
            for (int k = 0; k < 4; k++) acc[i][j][k] = 0.f;

    load_stage(0, 0);
    load_stage(1, 1);

    const int a_m = wm * 64 + (lane & 15);                            // + mf*16
    const int b_n = wn * 64 + ((lane >> 3) & 1) * 8 + (lane & 7);     // + p*16
    const int k8l = lane >> 4;                                        // k8 half

    for (int c = 0; c < NC; c++) {
        // entry: committed groups <= c+1; need group c done.
        if (c >= NC - 1) { CP_WAIT0(); } else { CP_WAIT1(); }
        __syncthreads();   // data of chunk c visible to all warps; also separates
                           // prior chunk's reads from the refill below.
        if (c + 2 < NC) load_stage(c + 2, (c + 2) % 3);

        uint32_t sb = sbu + (c % 3) * STG;
#pragma unroll
        for (int ks = 0; ks < 4; ks++) {     // four k16 steps in BK=64
            int seg = ks * 2 + k8l;
            uint32_t A[4][4], B[4][4];
#pragma unroll
            for (int mf = 0; mf < 4; mf++) {
                int m = a_m + mf * 16;
                LDSM_X4(A[mf], sb + m * 128 + ((seg ^ (m & 7)) << 4));
            }
#pragma unroll
            for (int p = 0; p < 4; p++) {
                int n = b_n + p * 16;
                LDSM_X4(B[p], sb + 16384 + n * 128 + ((seg ^ (n & 7)) << 4));
            }
#pragma unroll
            for (int mf = 0; mf < 4; mf++) {
#pragma unroll
                for (int p = 0; p < 4; p++) {
                    MMA_F16(acc[mf][2 * p + 0], A[mf], B[p][0], B[p][2]);
                    MMA_F16(acc[mf][2 * p + 1], A[mf], B[p][1], B[p][3]);
                }
            }
        }
    }

    // ---- epilogue --------------------------------------------------------------
    const int g = lane >> 2, q = lane & 3;
    if (IS_G1) {
#pragma unroll
        for (int mf = 0; mf < 4; mf++) {
#pragma unroll
            for (int h = 0; h < 2; h++) {
                int slotrow = mt * 128 + wm * 64 + mf * 16 + g + h * 8;
                size_t rowbase = ((size_t)e * CAP + slotrow) * H_DIM;
#pragma unroll
                for (int nf = 0; nf < 8; nf++) {
                    int col = nt * 128 + wn * 64 + nf * 8 + q * 2;
                    float v0 = fmaxf(acc[mf][nf][2 * h + 0] + __ldg(&bias[e * NTOT + col]),     0.f);
                    float v1 = fmaxf(acc[mf][nf][2 * h + 1] + __ldg(&bias[e * NTOT + col + 1]), 0.f);
                    __half2 hh = __floats2half2_rn(v0, v1);
                    *reinterpret_cast<uint32_t*>(&g_h[rowbase + col]) =
                        *reinterpret_cast<uint32_t*>(&hh);
                }
            }
        }
    } else {
#pragma unroll
        for (int mf = 0; mf < 4; mf++) {
#pragma unroll
            for (int h = 0; h < 2; h++) {
                int slotrow = mt * 128 + wm * 64 + mf * 16 + g + h * 8;
                int token = g_slot[e * CAP + slotrow];
                if (token < 0) continue;
                float gt = g_gate[token];
                float* orow = out + (size_t)token * M_DIM;
#pragma unroll
                for (int nf = 0; nf < 8; nf++) {
                    int col = nt * 128 + wn * 64 + nf * 8 + q * 2;
                    float2 v;
                    v.x = (acc[mf][nf][2 * h + 0] + __ldg(&bias[e * NTOT + col]))     * gt;
                    v.y = (acc[mf][nf][2 * h + 1] + __ldg(&bias[e * NTOT + col + 1])) * gt;
                    *(float2*)(orow + col) = v;
                }
            }
        }
    }
}

// ---------------- launch --------------------------------------------------------
extern "C" void kernel_launch(void* const* d_in, const int* in_sizes, int n_in,
                              void* d_out, int out_size) {
    const float* hs = (const float*)d_in[0];
    const float* wg = (const float*)d_in[1];
    const float* w1 = (const float*)d_in[2];   // [E, M, H]
    const float* b1 = (const float*)d_in[3];
    const float* w2 = (const float*)d_in[4];   // [E, H, M]
    const float* b2 = (const float*)d_in[5];
    float* out = (float*)d_out;

    constexpr int SMEM_BYTES = 3 * 32768;
    cudaFuncSetAttribute(moe_gemm_f16<M_DIM, true>,
                         cudaFuncAttributeMaxDynamicSharedMemorySize, SMEM_BYTES);
    cudaFuncSetAttribute(moe_gemm_f16<H_DIM, false>,
                         cudaFuncAttributeMaxDynamicSharedMemorySize, SMEM_BYTES);

    __half *a_p, *h_p, *w1t_p, *w2t_p;
    cudaGetSymbolAddress((void**)&a_p,   g_a);
    cudaGetSymbolAddress((void**)&h_p,   g_h);
    cudaGetSymbolAddress((void**)&w1t_p, g_w1t);
    cudaGetSymbolAddress((void**)&w2t_p, g_w2t);

    int write_laux = (out_size > S_TOK * M_DIM) ? 1 : 0;

    gate_kernel<<<S_TOK / 8, 256>>>(hs, wg);
    scan_kernel<<<1, 1024>>>(out + (size_t)S_TOK * M_DIM, write_laux);
    transpose_half_kernel<<<dim3(H_DIM / 32, M_DIM / 32, N_EXP), dim3(32, 8)>>>(
        w1, w1t_p, M_DIM, H_DIM);   // [E,M,H] -> [E,H,M]
    transpose_half_kernel<<<dim3(M_DIM / 32, H_DIM / 32, N_EXP), dim3(32, 8)>>>(
        w2, w2t_p, H_DIM, M_DIM);   // [E,H,M] -> [E,M,H]
    gather_half_kernel<<<N_EXP * CAP, 128>>>(hs);
    zero_dropped_kernel<<<S_TOK / 8, 256>>>(out);

    moe_gemm_f16<M_DIM, true><<<dim3(H_DIM / 128, CAP / 128, N_EXP), 128, SMEM_BYTES>>>(
        a_p, w1t_p, b1, nullptr);
    moe_gemm_f16<H_DIM, false><<<dim3(M_DIM / 128, CAP / 128, N_EXP), 128, SMEM_BYTES>>>(
        h_p, w2t_p, b2, out);
}

// round 12
// speedup vs baseline: 4.7398x; 1.0540x over previous
#include <cuda_runtime.h>
#include <cuda_bf16.h>
#include <cuda_fp16.h>
#include <cstdint>
#include <cstddef>

// Problem constants
#define S_TOK 8192
#define M_DIM 512
#define H_DIM 1024
#define N_EXP 8
#define CAP   1024

// ---------------- portable PTX helpers (sm_103 baseline) ------------------------
__device__ __forceinline__ uint32_t smem_to_u32(const void* p) {
    uint32_t a;
    asm("{ .reg .u64 t; cvta.to.shared.u64 t, %1; cvt.u32.u64 %0, t; }" : "=r"(a) : "l"(p));
    return a;
}
#define CP_ASYNC16(dst, src) \
    asm volatile("cp.async.cg.shared.global [%0], [%1], 16;" :: "r"(dst), "l"(src))
#define CP_COMMIT() asm volatile("cp.async.commit_group;" ::: "memory")
#define CP_WAIT1()  asm volatile("cp.async.wait_group 1;" ::: "memory")
#define CP_WAIT0()  asm volatile("cp.async.wait_group 0;" ::: "memory")
#define LDSM_X4(r, addr) \
    asm volatile("ldmatrix.sync.aligned.m8n8.x4.shared.b16 {%0,%1,%2,%3}, [%4];" \
        : "=r"((r)[0]), "=r"((r)[1]), "=r"((r)[2]), "=r"((r)[3]) : "r"(addr))
#define MMA_F16(c, a, b0, b1) \
    asm volatile("mma.sync.aligned.m16n8k16.row.col.f32.f16.f16.f32 " \
        "{%0,%1,%2,%3}, {%4,%5,%6,%7}, {%8,%9}, {%0,%1,%2,%3};" \
        : "+f"((c)[0]), "+f"((c)[1]), "+f"((c)[2]), "+f"((c)[3]) \
        : "r"((a)[0]), "r"((a)[1]), "r"((a)[2]), "r"((a)[3]), "r"(b0), "r"(b1))

// ---------------- device scratch ------------------------------------------------
__device__ __half g_a[(size_t)N_EXP * CAP * M_DIM];            // gathered tokens fp16
__device__ __half g_h[(size_t)N_EXP * CAP * H_DIM];            // hidden fp16
__device__ __half g_w1t[(size_t)N_EXP * H_DIM * M_DIM];        // w1^T fp16 [E,H,M]
__device__ __half g_w2t[(size_t)N_EXP * M_DIM * H_DIM];        // w2^T fp16 [E,M,H]
__device__ float g_gates[(size_t)S_TOK * N_EXP];
__device__ float g_gate[S_TOK];
__device__ int   g_expert[S_TOK];
__device__ int   g_loc[S_TOK];
__device__ int   g_slot[N_EXP * CAP];

// ---------------- 1) fused prep: gate + both weight transposes ------------------
// Block roles (one launch; blocks are independent so they overlap across SMs):
//   [0, 1024)        : gating for 8 tokens each
//   [1024, 5120)     : w1 [E,M,H] -> w1t [E,H,M] 32x32 tiles, fp32->fp16
//   [5120, 9216)     : w2 [E,H,M] -> w2t [E,M,H]
__global__ void prep_kernel(const float* __restrict__ feats, const float* __restrict__ wg,
                            const float* __restrict__ w1, const float* __restrict__ w2) {
    __shared__ float sh[N_EXP * M_DIM];   // 16KB; transpose role uses first 1056 floats
    int bid = blockIdx.x;
    int tid = threadIdx.x;

    if (bid < S_TOK / 8) {
        // ---- gate role ----
        for (int i = tid; i < N_EXP * M_DIM; i += 256) {
            int m = i & (M_DIM - 1);
            int e = i >> 9;
            sh[e * M_DIM + m] = wg[m * N_EXP + e];
        }
        __syncthreads();
        int warp = tid >> 5, lane = tid & 31;
        int s = bid * 8 + warp;
        const float* frow = feats + (size_t)s * M_DIM;
        float x[16];
#pragma unroll
        for (int j = 0; j < 16; j++) x[j] = frow[lane + 32 * j];
        float logit[N_EXP];
#pragma unroll
        for (int e = 0; e < N_EXP; e++) {
            const float* w = sh + e * M_DIM;
            float acc = 0.f;
#pragma unroll
            for (int j = 0; j < 16; j++) acc += x[j] * w[lane + 32 * j];
#pragma unroll
            for (int off = 16; off > 0; off >>= 1)
                acc += __shfl_down_sync(0xffffffffu, acc, off);
            logit[e] = acc;
        }
        if (lane == 0) {
            float mx = logit[0]; int am = 0;
#pragma unroll
            for (int e = 1; e < N_EXP; e++)
                if (logit[e] > mx) { mx = logit[e]; am = e; }
            float ex[N_EXP]; float se = 0.f;
#pragma unroll
            for (int e = 0; e < N_EXP; e++) { ex[e] = expf(logit[e] - mx); se += ex[e]; }
            float inv = 1.f / se;
#pragma unroll
            for (int e = 0; e < N_EXP; e++) g_gates[(size_t)s * N_EXP + e] = ex[e] * inv;
            g_expert[s] = am;
            g_gate[s]   = ex[am] * inv;
        }
        return;
    }

    // ---- transpose role ----
    int tb = bid - S_TOK / 8;
    const float* in; __half* outw; int R, C, cx, cy, e;
    __half *w1t_p = g_w1t, *w2t_p = g_w2t;
    if (tb < 4096) {                         // w1: R=M_DIM rows, C=H_DIM cols
        in = w1; outw = w1t_p; R = M_DIM; C = H_DIM;
        cx = tb & 31; cy = (tb >> 5) & 15; e = tb >> 9;       // grid (32, 16, 8)
    } else {                                 // w2: R=H_DIM rows, C=M_DIM cols
        tb -= 4096;
        in = w2; outw = w2t_p; R = H_DIM; C = M_DIM;
        cx = tb & 15; cy = (tb >> 4) & 31; e = tb >> 9;       // grid (16, 32, 8)
    }
    int r0 = cy * 32, c0 = cx * 32;
    float (*t)[33] = (float(*)[33])sh;
    int tx = tid & 31, ty = tid >> 5;        // 32 x 8
    const float* ine = in + (size_t)e * R * C;
#pragma unroll
    for (int i = 0; i < 4; i++)
        t[ty + i * 8][tx] = ine[(size_t)(r0 + ty + i * 8) * C + c0 + tx];
    __syncthreads();
    __half* oe = outw + (size_t)e * R * C;
#pragma unroll
    for (int it = 0; it < 2; it++) {
        int idx = it * 256 + tid;            // 0..511
        int ci  = idx >> 4;                  // 0..31 output row (old col)
        int rp  = (idx & 15) * 2;            // output col pair (old rows)
        __half2 v = __floats2half2_rn(t[rp][ci], t[rp + 1][ci]);
        *(__half2*)(oe + (size_t)(c0 + ci) * R + r0 + rp) = v;
    }
}

// ---------------- 2) parallel capacity scan + fused l_aux -----------------------
__global__ void scan_kernel(float* __restrict__ laux_out, int write_laux) {
    __shared__ int sexp[S_TOK];          // 32KB
    __shared__ int cnt[32][N_EXP];
    __shared__ int off[32][N_EXP];
    __shared__ int tot[N_EXP];
    __shared__ float red[1024];
    int tid = threadIdx.x;
    int warp = tid >> 5, lane = tid & 31;
    unsigned ltmask = (lane == 0) ? 0u : (0xffffffffu >> (32 - lane));

    for (int i = tid; i < S_TOK; i += 1024) sexp[i] = g_expert[i];
    for (int i = tid; i < N_EXP * CAP; i += 1024) g_slot[i] = -1;
    __syncthreads();

    // Phase 1: counts
    {
        int run[N_EXP];
#pragma unroll
        for (int e = 0; e < N_EXP; e++) run[e] = 0;
#pragma unroll
        for (int it = 0; it < 8; it++) {
            int s = warp * 256 + it * 32 + lane;
            int e = sexp[s];
#pragma unroll
            for (int eq = 0; eq < N_EXP; eq++) {
                unsigned bal = __ballot_sync(0xffffffffu, e == eq);
                run[eq] += __popc(bal);
            }
        }
        if (lane < N_EXP) cnt[warp][lane] = run[lane];
    }
    __syncthreads();

    // Phase 2: exclusive prefix + totals
    if (tid < 256) {
        int w = tid >> 3, e = tid & 7;
        int acc = 0;
        for (int wp = 0; wp < w; wp++) acc += cnt[wp][e];
        off[w][e] = acc;
        if (w == 31) tot[e] = acc + cnt[31][e];
    }
    __syncthreads();

    // Phase 3: assignment
    {
        int run[N_EXP];
#pragma unroll
        for (int e = 0; e < N_EXP; e++) run[e] = off[warp][e];
#pragma unroll
        for (int it = 0; it < 8; it++) {
            int s = warp * 256 + it * 32 + lane;
            int e = sexp[s];
            int myrank = 0;
            unsigned bals[N_EXP];
#pragma unroll
            for (int eq = 0; eq < N_EXP; eq++) {
                bals[eq] = __ballot_sync(0xffffffffu, e == eq);
                if (e == eq) myrank = __popc(bals[eq] & ltmask);
            }
            int loc = run[e] + myrank;
            g_loc[s] = loc;
            if (loc < CAP) g_slot[e * CAP + loc] = s;
#pragma unroll
            for (int eq = 0; eq < N_EXP; eq++) run[eq] += __popc(bals[eq]);
        }
    }

    // Fused l_aux
    if (!write_laux) return;
    float w[N_EXP];
#pragma unroll
    for (int e = 0; e < N_EXP; e++) w[e] = (float)min(tot[e], CAP);
    float acc = 0.f;
    for (int s = tid; s < S_TOK; s += 1024) {
        const float4* gp = (const float4*)(g_gates + (size_t)s * N_EXP);
        float4 a = gp[0], b = gp[1];
        acc += a.x * w[0] + a.y * w[1] + a.z * w[2] + a.w * w[3]
             + b.x * w[4] + b.y * w[5] + b.z * w[6] + b.w * w[7];
    }
    red[tid] = acc;
    __syncthreads();
    for (int st = 512; st > 0; st >>= 1) {
        if (tid < st) red[tid] += red[tid + st];
        __syncthreads();
    }
    if (tid == 0)
        *laux_out = red[0] * (float)N_EXP / ((float)S_TOK * (float)S_TOK);
}

// ---------------- 3) fused gather + zero-dropped --------------------------------
// Block roles: [0, 8192) gather slot rows -> fp16 A; [8192, 10240) zero dropped
// token rows (4 tokens per 128-thread block).
__global__ void gather_zero_kernel(const float* __restrict__ feats, float* __restrict__ out) {
    int bid = blockIdx.x;
    int tid = threadIdx.x;   // 128
    if (bid < N_EXP * CAP) {
        int token = g_slot[bid];
        float4 v = make_float4(0.f, 0.f, 0.f, 0.f);
        if (token >= 0) v = ((const float4*)(feats + (size_t)token * M_DIM))[tid];
        __half2 h01 = __floats2half2_rn(v.x, v.y);
        __half2 h23 = __floats2half2_rn(v.z, v.w);
        uint2 hv;
        hv.x = *reinterpret_cast<uint32_t*>(&h01);
        hv.y = *reinterpret_cast<uint32_t*>(&h23);
        ((uint2*)(g_a + (size_t)bid * M_DIM))[tid] = hv;
    } else {
        int s = (bid - N_EXP * CAP) * 4 + (tid >> 5);
        if (g_loc[s] < CAP) return;
        int lane = tid & 31;
        float4* row = (float4*)(out + (size_t)s * M_DIM);
#pragma unroll
        for (int i = 0; i < 4; i++)
            row[lane + 32 * i] = make_float4(0.f, 0.f, 0.f, 0.f);
    }
}

// ---------------- 4) single-pass fp16 GEMM via mma.sync -------------------------
// CTA tile 128x128, BK=64, 3-stage cp.async pipeline, 128 threads, 2 CTAs/SM.
// 4 warps as 2(m) x 2(n); warp tile 64x64. One barrier per chunk; refill issued
// before the chunk's MMAs so copies overlap compute.
template <int KTOT, bool IS_G1>
__global__ void __launch_bounds__(128, 2)
moe_gemm_f16(const __half* __restrict__ a_in, const __half* __restrict__ b_in,
             const float* __restrict__ bias, float* __restrict__ out) {
    constexpr int NTOT = IS_G1 ? H_DIM : M_DIM;
    constexpr int BK = 64;
    constexpr int NC = KTOT / BK;
    constexpr int STG = 32768;
    extern __shared__ __align__(1024) char smem[];
    const uint32_t sbu = smem_to_u32(smem);

    const int t = threadIdx.x;
    const int lane = t & 31, wid = t >> 5;
    const int wm = wid >> 1, wn = wid & 1;
    const int e = blockIdx.z, mt = blockIdx.y, nt = blockIdx.x;

    const __half* srcs[2] = {
        a_in + ((size_t)e * CAP  + mt * 128) * KTOT,
        b_in + ((size_t)e * NTOT + nt * 128) * KTOT};

    auto load_stage = [&](int c, int stg) {
        int k0 = c * BK;
        uint32_t sb = sbu + stg * STG;
#pragma unroll
        for (int i = 0; i < 16; i++) {
            int idx  = i * 128 + t;
            int tile = idx >> 10;           // 0..1
            int rem  = idx & 1023;
            int row  = rem >> 3;            // 0..127
            int seg  = rem & 7;             // 0..7 (16B units)
            const __half* src = srcs[tile] + (size_t)row * KTOT + k0 + seg * 8;
            uint32_t dst = sb + tile * 16384 + row * 128 + (((seg ^ (row & 7))) << 4);
            CP_ASYNC16(dst, src);
        }
        CP_COMMIT();
    };

    float acc[4][8][4];
#pragma unroll
    for (int i = 0; i < 4; i++)
#pragma unroll
        for (int j = 0; j < 8; j++)
#pragma unroll
            for (int k = 0; k < 4; k++) acc[i][j][k] = 0.f;

    load_stage(0, 0);
    load_stage(1, 1);

    const int a_m = wm * 64 + (lane & 15);                            // + mf*16
    const int b_n = wn * 64 + ((lane >> 3) & 1) * 8 + (lane & 7);     // + p*16
    const int k8l = lane >> 4;                                        // k8 half

    for (int c = 0; c < NC; c++) {
        if (c >= NC - 1) { CP_WAIT0(); } else { CP_WAIT1(); }
        __syncthreads();
        if (c + 2 < NC) load_stage(c + 2, (c + 2) % 3);

        uint32_t sb = sbu + (c % 3) * STG;
#pragma unroll
        for (int ks = 0; ks < 4; ks++) {
            int seg = ks * 2 + k8l;
            uint32_t A[4][4], B[4][4];
#pragma unroll
            for (int mf = 0; mf < 4; mf++) {
                int m = a_m + mf * 16;
                LDSM_X4(A[mf], sb + m * 128 + ((seg ^ (m & 7)) << 4));
            }
#pragma unroll
            for (int p = 0; p < 4; p++) {
                int n = b_n + p * 16;
                LDSM_X4(B[p], sb + 16384 + n * 128 + ((seg ^ (n & 7)) << 4));
            }
#pragma unroll
            for (int mf = 0; mf < 4; mf++) {
#pragma unroll
                for (int p = 0; p < 4; p++) {
                    MMA_F16(acc[mf][2 * p + 0], A[mf], B[p][0], B[p][2]);
                    MMA_F16(acc[mf][2 * p + 1], A[mf], B[p][1], B[p][3]);
                }
            }
        }
    }

    // ---- epilogue --------------------------------------------------------------
    const int g = lane >> 2, q = lane & 3;
    if (IS_G1) {
#pragma unroll
        for (int mf = 0; mf < 4; mf++) {
#pragma unroll
            for (int h = 0; h < 2; h++) {
                int slotrow = mt * 128 + wm * 64 + mf * 16 + g + h * 8;
                size_t rowbase = ((size_t)e * CAP + slotrow) * H_DIM;
#pragma unroll
                for (int nf = 0; nf < 8; nf++) {
                    int col = nt * 128 + wn * 64 + nf * 8 + q * 2;
                    float v0 = fmaxf(acc[mf][nf][2 * h + 0] + __ldg(&bias[e * NTOT + col]),     0.f);
                    float v1 = fmaxf(acc[mf][nf][2 * h + 1] + __ldg(&bias[e * NTOT + col + 1]), 0.f);
                    __half2 hh = __floats2half2_rn(v0, v1);
                    *reinterpret_cast<uint32_t*>(&g_h[rowbase + col]) =
                        *reinterpret_cast<uint32_t*>(&hh);
                }
            }
        }
    } else {
#pragma unroll
        for (int mf = 0; mf < 4; mf++) {
#pragma unroll
            for (int h = 0; h < 2; h++) {
                int slotrow = mt * 128 + wm * 64 + mf * 16 + g + h * 8;
                int token = g_slot[e * CAP + slotrow];
                if (token < 0) continue;
                float gt = g_gate[token];
                float* orow = out + (size_t)token * M_DIM;
#pragma unroll
                for (int nf = 0; nf < 8; nf++) {
                    int col = nt * 128 + wn * 64 + nf * 8 + q * 2;
                    float2 v;
                    v.x = (acc[mf][nf][2 * h + 0] + __ldg(&bias[e * NTOT + col]))     * gt;
                    v.y = (acc[mf][nf][2 * h + 1] + __ldg(&bias[e * NTOT + col + 1])) * gt;
                    *(float2*)(orow + col) = v;
                }
            }
        }
    }
}

// ---------------- launch --------------------------------------------------------
extern "C" void kernel_launch(void* const* d_in, const int* in_sizes, int n_in,
                              void* d_out, int out_size) {
    const float* hs = (const float*)d_in[0];
    const float* wg = (const float*)d_in[1];
    const float* w1 = (const float*)d_in[2];   // [E, M, H]
    const float* b1 = (const float*)d_in[3];
    const float* w2 = (const float*)d_in[4];   // [E, H, M]
    const float* b2 = (const float*)d_in[5];
    float* out = (float*)d_out;

    constexpr int SMEM_BYTES = 3 * 32768;
    cudaFuncSetAttribute(moe_gemm_f16<M_DIM, true>,
                         cudaFuncAttributeMaxDynamicSharedMemorySize, SMEM_BYTES);
    cudaFuncSetAttribute(moe_gemm_f16<H_DIM, false>,
                         cudaFuncAttributeMaxDynamicSharedMemorySize, SMEM_BYTES);

    __half *a_p, *h_p, *w1t_p, *w2t_p;
    cudaGetSymbolAddress((void**)&a_p,   g_a);
    cudaGetSymbolAddress((void**)&h_p,   g_h);
    cudaGetSymbolAddress((void**)&w1t_p, g_w1t);
    cudaGetSymbolAddress((void**)&w2t_p, g_w2t);

    int write_laux = (out_size > S_TOK * M_DIM) ? 1 : 0;

    // 1) gate + both weight transposes in ONE launch (block-role dispatch)
    prep_kernel<<<S_TOK / 8 + 4096 + 4096, 256>>>(hs, wg, w1, w2);
    // 2) capacity scan + fused l_aux
    scan_kernel<<<1, 1024>>>(out + (size_t)S_TOK * M_DIM, write_laux);
    // 3) gather + zero-dropped in ONE launch
    gather_zero_kernel<<<N_EXP * CAP + S_TOK / 4, 128>>>(hs, out);
    // 4) expert FFN
    moe_gemm_f16<M_DIM, true><<<dim3(H_DIM / 128, CAP / 128, N_EXP), 128, SMEM_BYTES>>>(
        a_p, w1t_p, b1, nullptr);
    moe_gemm_f16<H_DIM, false><<<dim3(M_DIM / 128, CAP / 128, N_EXP), 128, SMEM_BYTES>>>(
        h_p, w2t_p, b2, out);
}

// round 13
// speedup vs baseline: 4.7573x; 1.0037x over previous
#include <cuda_runtime.h>
#include <cuda_bf16.h>
#include <cuda_fp16.h>
#include <cstdint>
#include <cstddef>

// Problem constants
#define S_TOK 8192
#define M_DIM 512
#define H_DIM 1024
#define N_EXP 8
#define CAP   1024

// ---------------- portable PTX helpers (sm_103 baseline) ------------------------
__device__ __forceinline__ uint32_t smem_to_u32(const void* p) {
    uint32_t a;
    asm("{ .reg .u64 t; cvta.to.shared.u64 t, %1; cvt.u32.u64 %0, t; }" : "=r"(a) : "l"(p));
    return a;
}
#define CP_ASYNC16(dst, src) \
    asm volatile("cp.async.cg.shared.global [%0], [%1], 16;" :: "r"(dst), "l"(src))
#define CP_COMMIT() asm volatile("cp.async.commit_group;" ::: "memory")
#define CP_WAIT1()  asm volatile("cp.async.wait_group 1;" ::: "memory")
#define CP_WAIT0()  asm volatile("cp.async.wait_group 0;" ::: "memory")
#define LDSM_X4(r, addr) \
    asm volatile("ldmatrix.sync.aligned.m8n8.x4.shared.b16 {%0,%1,%2,%3}, [%4];" \
        : "=r"((r)[0]), "=r"((r)[1]), "=r"((r)[2]), "=r"((r)[3]) : "r"(addr))
#define MMA_F16(c, a, b0, b1) \
    asm volatile("mma.sync.aligned.m16n8k16.row.col.f32.f16.f16.f32 " \
        "{%0,%1,%2,%3}, {%4,%5,%6,%7}, {%8,%9}, {%0,%1,%2,%3};" \
        : "+f"((c)[0]), "+f"((c)[1]), "+f"((c)[2]), "+f"((c)[3]) \
        : "r"((a)[0]), "r"((a)[1]), "r"((a)[2]), "r"((a)[3]), "r"(b0), "r"(b1))

// ---------------- device scratch ------------------------------------------------
__device__ __half g_a[(size_t)N_EXP * CAP * M_DIM];            // gathered tokens fp16
__device__ __half g_h[(size_t)N_EXP * CAP * H_DIM];            // hidden fp16
__device__ __half g_w1t[(size_t)N_EXP * H_DIM * M_DIM];        // w1^T fp16 [E,H,M]
__device__ __half g_w2t[(size_t)N_EXP * M_DIM * H_DIM];        // w2^T fp16 [E,M,H]
__device__ float g_gates[(size_t)S_TOK * N_EXP];
__device__ float g_gate[S_TOK];
__device__ int   g_expert[S_TOK];
__device__ int   g_loc[S_TOK];
__device__ int   g_slot[N_EXP * CAP];

// ---------------- 1) fused prep: gate + w1 transpose ----------------------------
// Block roles: [0,1024) gate (8 tokens each); [1024,5120) w1 [E,M,H]->[E,H,M].
__global__ void prep_kernel(const float* __restrict__ feats, const float* __restrict__ wg,
                            const float* __restrict__ w1) {
    __shared__ float sh[N_EXP * M_DIM];   // 16KB
    int bid = blockIdx.x;
    int tid = threadIdx.x;

    if (bid < S_TOK / 8) {
        // ---- gate role ----
        for (int i = tid; i < N_EXP * M_DIM; i += 256) {
            int m = i & (M_DIM - 1);
            int e = i >> 9;
            sh[e * M_DIM + m] = wg[m * N_EXP + e];
        }
        __syncthreads();
        int warp = tid >> 5, lane = tid & 31;
        int s = bid * 8 + warp;
        const float* frow = feats + (size_t)s * M_DIM;
        float x[16];
#pragma unroll
        for (int j = 0; j < 16; j++) x[j] = frow[lane + 32 * j];
        float logit[N_EXP];
#pragma unroll
        for (int e = 0; e < N_EXP; e++) {
            const float* w = sh + e * M_DIM;
            float acc = 0.f;
#pragma unroll
            for (int j = 0; j < 16; j++) acc += x[j] * w[lane + 32 * j];
#pragma unroll
            for (int off = 16; off > 0; off >>= 1)
                acc += __shfl_down_sync(0xffffffffu, acc, off);
            logit[e] = acc;
        }
        if (lane == 0) {
            float mx = logit[0]; int am = 0;
#pragma unroll
            for (int e = 1; e < N_EXP; e++)
                if (logit[e] > mx) { mx = logit[e]; am = e; }
            float ex[N_EXP]; float se = 0.f;
#pragma unroll
            for (int e = 0; e < N_EXP; e++) { ex[e] = expf(logit[e] - mx); se += ex[e]; }
            float inv = 1.f / se;
#pragma unroll
            for (int e = 0; e < N_EXP; e++) g_gates[(size_t)s * N_EXP + e] = ex[e] * inv;
            g_expert[s] = am;
            g_gate[s]   = ex[am] * inv;
        }
        return;
    }

    // ---- w1 transpose role: R=M_DIM rows, C=H_DIM cols, grid (32, 16, 8) -------
    int tb = bid - S_TOK / 8;
    const int R = M_DIM, C = H_DIM;
    int cx = tb & 31, cy = (tb >> 5) & 15, e = tb >> 9;
    int r0 = cy * 32, c0 = cx * 32;
    float (*t)[33] = (float(*)[33])sh;
    int tx = tid & 31, ty = tid >> 5;        // 32 x 8
    const float* ine = w1 + (size_t)e * R * C;
#pragma unroll
    for (int i = 0; i < 4; i++)
        t[ty + i * 8][tx] = ine[(size_t)(r0 + ty + i * 8) * C + c0 + tx];
    __syncthreads();
    __half* oe = g_w1t + (size_t)e * R * C;
#pragma unroll
    for (int it = 0; it < 2; it++) {
        int idx = it * 256 + tid;
        int ci  = idx >> 4;
        int rp  = (idx & 15) * 2;
        __half2 v = __floats2half2_rn(t[rp][ci], t[rp + 1][ci]);
        *(__half2*)(oe + (size_t)(c0 + ci) * R + r0 + rp) = v;
    }
}

// ---------------- 2) parallel capacity scan + fused l_aux -----------------------
__global__ void scan_kernel(float* __restrict__ laux_out, int write_laux) {
    __shared__ int sexp[S_TOK];          // 32KB
    __shared__ int cnt[32][N_EXP];
    __shared__ int off[32][N_EXP];
    __shared__ int tot[N_EXP];
    __shared__ float red[1024];
    int tid = threadIdx.x;
    int warp = tid >> 5, lane = tid & 31;
    unsigned ltmask = (lane == 0) ? 0u : (0xffffffffu >> (32 - lane));

    for (int i = tid; i < S_TOK; i += 1024) sexp[i] = g_expert[i];
    for (int i = tid; i < N_EXP * CAP; i += 1024) g_slot[i] = -1;
    __syncthreads();

    // Phase 1: counts
    {
        int run[N_EXP];
#pragma unroll
        for (int e = 0; e < N_EXP; e++) run[e] = 0;
#pragma unroll
        for (int it = 0; it < 8; it++) {
            int s = warp * 256 + it * 32 + lane;
            int e = sexp[s];
#pragma unroll
            for (int eq = 0; eq < N_EXP; eq++) {
                unsigned bal = __ballot_sync(0xffffffffu, e == eq);
                run[eq] += __popc(bal);
            }
        }
        if (lane < N_EXP) cnt[warp][lane] = run[lane];
    }
    __syncthreads();

    // Phase 2: exclusive prefix + totals
    if (tid < 256) {
        int w = tid >> 3, e = tid & 7;
        int acc = 0;
        for (int wp = 0; wp < w; wp++) acc += cnt[wp][e];
        off[w][e] = acc;
        if (w == 31) tot[e] = acc + cnt[31][e];
    }
    __syncthreads();

    // Phase 3: assignment
    {
        int run[N_EXP];
#pragma unroll
        for (int e = 0; e < N_EXP; e++) run[e] = off[warp][e];
#pragma unroll
        for (int it = 0; it < 8; it++) {
            int s = warp * 256 + it * 32 + lane;
            int e = sexp[s];
            int myrank = 0;
            unsigned bals[N_EXP];
#pragma unroll
            for (int eq = 0; eq < N_EXP; eq++) {
                bals[eq] = __ballot_sync(0xffffffffu, e == eq);
                if (e == eq) myrank = __popc(bals[eq] & ltmask);
            }
            int loc = run[e] + myrank;
            g_loc[s] = loc;
            if (loc < CAP) g_slot[e * CAP + loc] = s;
#pragma unroll
            for (int eq = 0; eq < N_EXP; eq++) run[eq] += __popc(bals[eq]);
        }
    }

    // Fused l_aux
    if (!write_laux) return;
    float w[N_EXP];
#pragma unroll
    for (int e = 0; e < N_EXP; e++) w[e] = (float)min(tot[e], CAP);
    float acc = 0.f;
    for (int s = tid; s < S_TOK; s += 1024) {
        const float4* gp = (const float4*)(g_gates + (size_t)s * N_EXP);
        float4 a = gp[0], b = gp[1];
        acc += a.x * w[0] + a.y * w[1] + a.z * w[2] + a.w * w[3]
             + b.x * w[4] + b.y * w[5] + b.z * w[6] + b.w * w[7];
    }
    red[tid] = acc;
    __syncthreads();
    for (int st = 512; st > 0; st >>= 1) {
        if (tid < st) red[tid] += red[tid + st];
        __syncthreads();
    }
    if (tid == 0)
        *laux_out = red[0] * (float)N_EXP / ((float)S_TOK * (float)S_TOK);
}

// ---------------- 3) fused gather + zero-dropped --------------------------------
__global__ void gather_zero_kernel(const float* __restrict__ feats, float* __restrict__ out) {
    int bid = blockIdx.x;
    int tid = threadIdx.x;   // 128
    if (bid < N_EXP * CAP) {
        int token = g_slot[bid];
        float4 v = make_float4(0.f, 0.f, 0.f, 0.f);
        if (token >= 0) v = ((const float4*)(feats + (size_t)token * M_DIM))[tid];
        __half2 h01 = __floats2half2_rn(v.x, v.y);
        __half2 h23 = __floats2half2_rn(v.z, v.w);
        uint2 hv;
        hv.x = *reinterpret_cast<uint32_t*>(&h01);
        hv.y = *reinterpret_cast<uint32_t*>(&h23);
        ((uint2*)(g_a + (size_t)bid * M_DIM))[tid] = hv;
    } else {
        int s = (bid - N_EXP * CAP) * 4 + (tid >> 5);
        if (g_loc[s] < CAP) return;
        int lane = tid & 31;
        float4* row = (float4*)(out + (size_t)s * M_DIM);
#pragma unroll
        for (int i = 0; i < 4; i++)
            row[lane + 32 * i] = make_float4(0.f, 0.f, 0.f, 0.f);
    }
}

// ---------------- 4) single-pass fp16 GEMM via mma.sync -------------------------
// 1D grid, block-role dispatch. bid < NTILES: 128x128 GEMM tile (BK=64, 3-stage
// cp.async, 4 warps 2x2 of 64x64, 2 CTAs/SM). For IS_G1, bids >= NTILES run the
// w2 [E,H,M]->[E,M,H] fp32->fp16 transpose (needed only by GEMM2) — these blocks
// fill GEMM1's second-wave tail and its idle DRAM bandwidth.
template <int KTOT, bool IS_G1>
__global__ void __launch_bounds__(128, 2)
moe_gemm_f16(const __half* __restrict__ a_in, const __half* __restrict__ b_in,
             const float* __restrict__ bias, float* __restrict__ out,
             const float* __restrict__ xpose_src) {
    constexpr int NTOT = IS_G1 ? H_DIM : M_DIM;
    constexpr int NTILES = (CAP / 128) * (NTOT / 128) * N_EXP;
    constexpr int BK = 64;
    constexpr int NC = KTOT / BK;
    constexpr int STG = 32768;
    extern __shared__ __align__(1024) char smem[];
    const int bid = blockIdx.x;
    const int t = threadIdx.x;

    if (IS_G1 && bid >= NTILES) {
        // ---- w2 transpose role: R=H_DIM rows, C=M_DIM cols, 32x32 tiles --------
        int tb = bid - NTILES;
        const int R = H_DIM, C = M_DIM;
        int cx = tb & 15, cy = (tb >> 4) & 31, e = tb >> 9;
        int r0 = cy * 32, c0 = cx * 32;
        float (*tt)[33] = (float(*)[33])smem;
        int tx = t & 31, ty = t >> 5;        // 32 x 4
        const float* ine = xpose_src + (size_t)e * R * C;
#pragma unroll
        for (int i = 0; i < 8; i++)
            tt[ty + i * 4][tx] = ine[(size_t)(r0 + ty + i * 4) * C + c0 + tx];
        __syncthreads();
        __half* oe = g_w2t + (size_t)e * R * C;
#pragma unroll
        for (int it = 0; it < 4; it++) {
            int idx = it * 128 + t;          // 0..511
            int ci  = idx >> 4;
            int rp  = (idx & 15) * 2;
            __half2 v = __floats2half2_rn(tt[rp][ci], tt[rp + 1][ci]);
            *(__half2*)(oe + (size_t)(c0 + ci) * R + r0 + rp) = v;
        }
        return;
    }

    const uint32_t sbu = smem_to_u32(smem);
    const int lane = t & 31, wid = t >> 5;
    const int wm = wid >> 1, wn = wid & 1;
    const int nt = bid % (NTOT / 128);
    const int mt = (bid / (NTOT / 128)) % (CAP / 128);
    const int e  = bid / ((NTOT / 128) * (CAP / 128));

    const __half* srcs[2] = {
        a_in + ((size_t)e * CAP  + mt * 128) * KTOT,
        b_in + ((size_t)e * NTOT + nt * 128) * KTOT};

    auto load_stage = [&](int c, int stg) {
        int k0 = c * BK;
        uint32_t sb = sbu + stg * STG;
#pragma unroll
        for (int i = 0; i < 16; i++) {
            int idx  = i * 128 + t;
            int tile = idx >> 10;           // 0..1
            int rem  = idx & 1023;
            int row  = rem >> 3;            // 0..127
            int seg  = rem & 7;             // 0..7 (16B units)
            const __half* src = srcs[tile] + (size_t)row * KTOT + k0 + seg * 8;
            uint32_t dst = sb + tile * 16384 + row * 128 + (((seg ^ (row & 7))) << 4);
            CP_ASYNC16(dst, src);
        }
        CP_COMMIT();
    };

    float acc[4][8][4];
#pragma unroll
    for (int i = 0; i < 4; i++)
#pragma unroll
        for (int j = 0; j < 8; j++)
#pragma unroll
            for (int k = 0; k < 4; k++) acc[i][j][k] = 0.f;

    load_stage(0, 0);
    load_stage(1, 1);

    const int a_m = wm * 64 + (lane & 15);                            // + mf*16
    const int b_n = wn * 64 + ((lane >> 3) & 1) * 8 + (lane & 7);     // + p*16
    const int k8l = lane >> 4;                                        // k8 half

    for (int c = 0; c < NC; c++) {
        if (c >= NC - 1) { CP_WAIT0(); } else { CP_WAIT1(); }
        __syncthreads();
        if (c + 2 < NC) load_stage(c + 2, (c + 2) % 3);

        uint32_t sb = sbu + (c % 3) * STG;
#pragma unroll
        for (int ks = 0; ks < 4; ks++) {
            int seg = ks * 2 + k8l;
            uint32_t A[4][4], B[4][4];
#pragma unroll
            for (int mf = 0; mf < 4; mf++) {
                int m = a_m + mf * 16;
                LDSM_X4(A[mf], sb + m * 128 + ((seg ^ (m & 7)) << 4));
            }
#pragma unroll
            for (int p = 0; p < 4; p++) {
                int n = b_n + p * 16;
                LDSM_X4(B[p], sb + 16384 + n * 128 + ((seg ^ (n & 7)) << 4));
            }
#pragma unroll
            for (int mf = 0; mf < 4; mf++) {
#pragma unroll
                for (int p = 0; p < 4; p++) {
                    MMA_F16(acc[mf][2 * p + 0], A[mf], B[p][0], B[p][2]);
                    MMA_F16(acc[mf][2 * p + 1], A[mf], B[p][1], B[p][3]);
                }
            }
        }
    }

    // ---- epilogue --------------------------------------------------------------
    const int g = lane >> 2, q = lane & 3;
    if (IS_G1) {
#pragma unroll
        for (int mf = 0; mf < 4; mf++) {
#pragma unroll
            for (int h = 0; h < 2; h++) {
                int slotrow = mt * 128 + wm * 64 + mf * 16 + g + h * 8;
                size_t rowbase = ((size_t)e * CAP + slotrow) * H_DIM;
#pragma unroll
                for (int nf = 0; nf < 8; nf++) {
                    int col = nt * 128 + wn * 64 + nf * 8 + q * 2;
                    float v0 = fmaxf(acc[mf][nf][2 * h + 0] + __ldg(&bias[e * NTOT + col]),     0.f);
                    float v1 = fmaxf(acc[mf][nf][2 * h + 1] + __ldg(&bias[e * NTOT + col + 1]), 0.f);
                    __half2 hh = __floats2half2_rn(v0, v1);
                    *reinterpret_cast<uint32_t*>(&g_h[rowbase + col]) =
                        *reinterpret_cast<uint32_t*>(&hh);
                }
            }
        }
    } else {
#pragma unroll
        for (int mf = 0; mf < 4; mf++) {
#pragma unroll
            for (int h = 0; h < 2; h++) {
                int slotrow = mt * 128 + wm * 64 + mf * 16 + g + h * 8;
                int token = g_slot[e * CAP + slotrow];
                if (token < 0) continue;
                float gt = g_gate[token];
                float* orow = out + (size_t)token * M_DIM;
#pragma unroll
                for (int nf = 0; nf < 8; nf++) {
                    int col = nt * 128 + wn * 64 + nf * 8 + q * 2;
                    float2 v;
                    v.x = (acc[mf][nf][2 * h + 0] + __ldg(&bias[e * NTOT + col]))     * gt;
                    v.y = (acc[mf][nf][2 * h + 1] + __ldg(&bias[e * NTOT + col + 1])) * gt;
                    *(float2*)(orow + col) = v;
                }
            }
        }
    }
}

// ---------------- launch --------------------------------------------------------
extern "C" void kernel_launch(void* const* d_in, const int* in_sizes, int n_in,
                              void* d_out, int out_size) {
    const float* hs = (const float*)d_in[0];
    const float* wg = (const float*)d_in[1];
    const float* w1 = (const float*)d_in[2];   // [E, M, H]
    const float* b1 = (const float*)d_in[3];
    const float* w2 = (const float*)d_in[4];   // [E, H, M]
    const float* b2 = (const float*)d_in[5];
    float* out = (float*)d_out;

    constexpr int SMEM_BYTES = 3 * 32768;
    cudaFuncSetAttribute(moe_gemm_f16<M_DIM, true>,
                         cudaFuncAttributeMaxDynamicSharedMemorySize, SMEM_BYTES);
    cudaFuncSetAttribute(moe_gemm_f16<H_DIM, false>,
                         cudaFuncAttributeMaxDynamicSharedMemorySize, SMEM_BYTES);

    __half *a_p, *h_p, *w1t_p, *w2t_p;
    cudaGetSymbolAddress((void**)&a_p,   g_a);
    cudaGetSymbolAddress((void**)&h_p,   g_h);
    cudaGetSymbolAddress((void**)&w1t_p, g_w1t);
    cudaGetSymbolAddress((void**)&w2t_p, g_w2t);

    int write_laux = (out_size > S_TOK * M_DIM) ? 1 : 0;

    // 1) gate + w1 transpose (one launch, block roles)
    prep_kernel<<<S_TOK / 8 + 4096, 256>>>(hs, wg, w1);
    // 2) capacity scan + fused l_aux
    scan_kernel<<<1, 1024>>>(out + (size_t)S_TOK * M_DIM, write_laux);
    // 3) gather + zero-dropped (one launch)
    gather_zero_kernel<<<N_EXP * CAP + S_TOK / 4, 128>>>(hs, out);
    // 4) GEMM1 (512 tiles) + w2 transpose blocks (4096) filling its tail
    moe_gemm_f16<M_DIM, true><<<512 + 4096, 128, SMEM_BYTES>>>(
        a_p, w1t_p, b1, nullptr, w2);
    // 5) GEMM2 (256 tiles)
    moe_gemm_f16<H_DIM, false><<<256, 128, SMEM_BYTES>>>(
        h_p, w2t_p, b2, out, nullptr);
}